// round 15
// baseline (speedup 1.0000x reference)
#include <cuda_runtime.h>
#include <cuda_fp16.h>
#include <math.h>
#include <stdint.h>

// ---------------------------------------------------------------------------
// B=4096, IN_DIM=1024, D=128, C=10000. seq_len==1 -> attn == v (q,k dead).
// Attention composed: xs = LN(t1 @ [W2@(Wp+I)] + b''), Wp = Wv@out_w.
// mma.sync fp16: x 2-term, t1/h 2-term, xs 3-term, head 1-term fp16 K=128.
// Head: merged kernel, A persists across planes; z=1 B prefetched under the
// z=0 epilogue. Batch split in halves: head(half1) overlaps FE(half2).
// ---------------------------------------------------------------------------

#define NB   4096
#define NH   2048          // half batch
#define NIN  1024
#define ND   128
#define NC   10000
#define NC2  10112

// ------------------------- device scratch (no allocs) ----------------------
__device__ float g_xs[NB * ND];
__device__ float g_e2[NB];
__device__ float g_de[NB];
__device__ float g_ke[NB];
__device__ float g_Wp[ND * ND];
__device__ float g_bp[ND];
__device__ float g_W2c[256 * ND];
__device__ float g_bc [ND];
__device__ uint4 g_xsp [NB * 2048 / 8];
__device__ uint4 g_t1sp[NB * 512  / 8];
__device__ uint4 g_xssp[NB * 384  / 8];
__device__ uint4 g_hsp [NB * 1024 / 8];
__device__ uint4 g_W1p [256 * 2048 / 8];
__device__ uint4 g_W2cp[128 * 512  / 8];
__device__ uint4 g_fw1p[512 * 384  / 8];
__device__ uint4 g_fw2p[128 * 1024 / 8];
__device__ uint4 g_Ay [NB  * 128 / 8];
__device__ uint4 g_B1e[NC2 * 128 / 8];
__device__ uint4 g_B2e[NC2 * 128 / 8];
__device__ float g_p2[NC2];
__device__ float g_dp[NC2];
__device__ float g_eb[NC2];

// ------------------------------ helpers ------------------------------------
static __device__ __forceinline__ uint32_t smem_u32(const void* p) {
    uint32_t a;
    asm("{ .reg .u64 t; cvta.to.shared.u64 t, %1; cvt.u32.u64 %0, t; }" : "=r"(a) : "l"(p));
    return a;
}
static __device__ __forceinline__ void cp_async16(uint32_t s, const void* g) {
    asm volatile("cp.async.cg.shared.global [%0], [%1], 16;" :: "r"(s), "l"(g) : "memory");
}
static __device__ __forceinline__ void ldmx4(uint32_t a, uint32_t& r0, uint32_t& r1,
                                             uint32_t& r2, uint32_t& r3) {
    asm volatile("ldmatrix.sync.aligned.m8n8.x4.shared.b16 {%0,%1,%2,%3}, [%4];"
                 : "=r"(r0), "=r"(r1), "=r"(r2), "=r"(r3) : "r"(a));
}
static __device__ __forceinline__ void mma_fp16(float* d, const uint32_t* a,
                                                uint32_t b0, uint32_t b1) {
    asm volatile("mma.sync.aligned.m16n8k16.row.col.f32.f16.f16.f32 "
                 "{%0,%1,%2,%3}, {%4,%5,%6,%7}, {%8,%9}, {%0,%1,%2,%3};"
                 : "+f"(d[0]), "+f"(d[1]), "+f"(d[2]), "+f"(d[3])
                 : "r"(a[0]), "r"(a[1]), "r"(a[2]), "r"(a[3]), "r"(b0), "r"(b1));
}
static __device__ __forceinline__ float gelu_exact(float x) {
    return 0.5f * x * (1.0f + erff(x * 0.70710678118654752440f));
}
static __device__ __forceinline__ float warp_sum(float v) {
#pragma unroll
    for (int o = 16; o > 0; o >>= 1) v += __shfl_xor_sync(0xffffffffu, v, o);
    return v;
}
static __device__ __forceinline__ float block_sum_128(float v) {
    __shared__ float sh[4];
    int lane = threadIdx.x & 31, wid = threadIdx.x >> 5;
    v = warp_sum(v);
    __syncthreads();
    if (lane == 0) sh[wid] = v;
    __syncthreads();
    return sh[0] + sh[1] + sh[2] + sh[3];
}
static __device__ __forceinline__ void curvature(const float* logc, float& c, float& sc) {
    float cc = expf(logc[0]);
    cc = fminf(fmaxf(cc, 1e-4f), 10.0f);
    cc = fmaxf(fabsf(cc), 1e-6f);
    c = cc; sc = sqrtf(cc);
}
static __device__ __forceinline__ void split_hl(float x, __half& h, __half& l) {
    h = __float2half_rn(x);
    l = __float2half_rn(x - __half2float(h));
}
static __device__ __forceinline__ void split4_store(const float* v, __half* hip, __half* lop) {
    __half h[4], l[4];
#pragma unroll
    for (int e = 0; e < 4; ++e) split_hl(v[e], h[e], l[e]);
    __half2 h01 = __halves2half2(h[0], h[1]), h23 = __halves2half2(h[2], h[3]);
    __half2 l01 = __halves2half2(l[0], l[1]), l23 = __halves2half2(l[2], l[3]);
    uint2 ph, pl;
    ph.x = *(uint32_t*)&h01; ph.y = *(uint32_t*)&h23;
    pl.x = *(uint32_t*)&l01; pl.y = *(uint32_t*)&l23;
    *(uint2*)hip = ph;
    *(uint2*)lop = pl;
}
static __device__ __forceinline__ void pack4_store(const float* v, __half* hip) {
    __half h[4];
#pragma unroll
    for (int e = 0; e < 4; ++e) h[e] = __float2half_rn(v[e]);
    __half2 h01 = __halves2half2(h[0], h[1]), h23 = __halves2half2(h[2], h[3]);
    uint2 ph; ph.x = *(uint32_t*)&h01; ph.y = *(uint32_t*)&h23;
    *(uint2*)hip = ph;
}

// ------------------- preps -------------------------------------------------
__global__ void asplit2(const float* __restrict__ X, __half* __restrict__ out,
                        int K, int base)
{
    int row = base + blockIdx.x;
    const float4* xr = (const float4*)(X + (size_t)row * K);
    __half* o = out + (size_t)row * 2 * K;
    for (int k4 = threadIdx.x; k4 < (K >> 2); k4 += 256) {
        float4 v = xr[k4];
        float* vp = &v.x;
        int k = k4 * 4;
        __half h[4], l[4];
#pragma unroll
        for (int e = 0; e < 4; ++e) split_hl(vp[e], h[e], l[e]);
        __half2 h01 = __halves2half2(h[0], h[1]), h23 = __halves2half2(h[2], h[3]);
        __half2 l01 = __halves2half2(l[0], l[1]), l23 = __halves2half2(l[2], l[3]);
        uint2 ph, pl;
        ph.x = *(uint32_t*)&h01; ph.y = *(uint32_t*)&h23;
        pl.x = *(uint32_t*)&l01; pl.y = *(uint32_t*)&l23;
        *(uint2*)(o + k) = ph;
        *(uint2*)(o + K + k) = pl;
    }
}
__global__ void __launch_bounds__(256) wprep(const float* __restrict__ W,
                                             __half* __restrict__ out, int K, int N)
{
    __shared__ float t[32][33];
    const int k0 = blockIdx.x * 32, n0 = blockIdx.y * 32;
    const int tx = threadIdx.x & 31, ty = threadIdx.x >> 5;
#pragma unroll
    for (int i = ty; i < 32; i += 8)
        t[i][tx] = W[(size_t)(k0 + i) * N + n0 + tx];
    __syncthreads();
#pragma unroll
    for (int i = ty; i < 32; i += 8) {
        int n = n0 + i, k = k0 + tx;
        __half h, l; split_hl(t[tx][i], h, l);
        size_t base = (size_t)n * 3 * K;
        out[base + k] = h; out[base + K + k] = h; out[base + 2 * K + k] = l;
    }
}
__global__ void __launch_bounds__(256) wprep2(const float* __restrict__ W,
                                              __half* __restrict__ out, int K, int N)
{
    __shared__ float t[32][33];
    const int k0 = blockIdx.x * 32, n0 = blockIdx.y * 32;
    const int tx = threadIdx.x & 31, ty = threadIdx.x >> 5;
#pragma unroll
    for (int i = ty; i < 32; i += 8)
        t[i][tx] = W[(size_t)(k0 + i) * N + n0 + tx];
    __syncthreads();
#pragma unroll
    for (int i = ty; i < 32; i += 8) {
        int n = n0 + i, k = k0 + tx;
        __half h = __float2half_rn(t[tx][i]);
        size_t base = (size_t)n * 2 * K;
        out[base + k] = h; out[base + K + k] = h;
    }
}
__global__ void fold_w(const float* __restrict__ in_w, const float* __restrict__ out_w,
                       const float* __restrict__ in_b, const float* __restrict__ out_b)
{
    int j = threadIdx.x;
    if (blockIdx.x < ND) {
        int k = blockIdx.x;
        float s = 0.f;
#pragma unroll 8
        for (int m = 0; m < ND; ++m)
            s = fmaf(in_w[k * 384 + 256 + m], out_w[m * ND + j], s);
        g_Wp[k * ND + j] = s;
    } else {
        float s = out_b[j];
#pragma unroll 8
        for (int m = 0; m < ND; ++m)
            s = fmaf(in_b[256 + m], out_w[m * ND + j], s);
        g_bp[j] = s;
    }
}
__global__ void fold2_w(const float* __restrict__ W2, const float* __restrict__ b2)
{
    int j = threadIdx.x;
    if (blockIdx.x < 256) {
        int k = blockIdx.x;
        float s = W2[k * ND + j];
#pragma unroll 8
        for (int m = 0; m < ND; ++m)
            s = fmaf(W2[k * ND + m], g_Wp[m * ND + j], s);
        g_W2c[k * ND + j] = s;
    } else {
        float s = g_bp[j] + b2[j];
#pragma unroll 8
        for (int m = 0; m < ND; ++m)
            s = fmaf(b2[m], g_Wp[m * ND + j], s);
        g_bc[j] = s;
    }
}
__global__ void proto_prep(const float* __restrict__ P, const float* __restrict__ logc)
{
    int row = blockIdx.x, tid = threadIdx.x;
    float p = (row < NC) ? P[(size_t)row * ND + tid] : 0.0f;
    float n2 = block_sum_128(p * p);
    float c, sc; curvature(logc, c, sc);
    float maxn = (1.0f - 1e-5f) / sc;
    float scl = fminf(maxn / fmaxf(sqrtf(n2), 1e-6f), 1.0f);
    p *= scl;
    __half* B1 = (__half*)g_B1e;
    B1[(size_t)row * 128 + tid] = __float2half_rn(p);
    if (tid == 0) {
        float p2 = n2 * scl * scl;
        g_p2[row] = p2;
        g_dp[row] = 1.0f - c * fminf(p2, 1.0f - 1e-5f);
    }
}
__global__ void __launch_bounds__(256) euc_prep(const float* __restrict__ W,
                                                const float* __restrict__ bias)
{
    __shared__ float tile[128 * 65];
    const int tid = threadIdx.x;
    const int c0 = blockIdx.x * 64;
#pragma unroll
    for (int it = 0; it < 32; ++it) {
        int idx = it * 256 + tid;
        int k = idx >> 6, cc = idx & 63;
        int cls = c0 + cc;
        tile[k * 65 + cc] = (cls < NC) ? W[(size_t)k * NC + cls] : 0.0f;
    }
    __syncthreads();
    const int cc = tid & 63, q = tid >> 6;
    __half* B2 = (__half*)g_B2e;
    const size_t base = (size_t)(c0 + cc) * 128;
#pragma unroll
    for (int j8 = 0; j8 < 4; ++j8) {
        int k = q * 32 + j8 * 8;
        __half2 hp[4];
#pragma unroll
        for (int e = 0; e < 4; ++e)
            hp[e] = __halves2half2(__float2half_rn(tile[(k + 2 * e) * 65 + cc]),
                                   __float2half_rn(tile[(k + 2 * e + 1) * 65 + cc]));
        uint4 pk;
        pk.x = *(uint32_t*)&hp[0]; pk.y = *(uint32_t*)&hp[1];
        pk.z = *(uint32_t*)&hp[2]; pk.w = *(uint32_t*)&hp[3];
        *(uint4*)(B2 + base + k) = pk;
    }
    if (tid < 64) {
        int cls = c0 + tid;
        g_eb[cls] = (cls < NC) ? bias[cls] : 0.0f;
    }
}

// ---------------- tensor GEMM, MT x 128 tile, fused epilogues ---------------
#define HSMEM 49152

template <int MT, int ACT, int EPI, int WF32, int WSP>
__global__ void __launch_bounds__(256, 2) hgemm(
    const __half* __restrict__ A, const __half* __restrict__ Bt,
    const float* __restrict__ bias,
    float* __restrict__ C, __half* __restrict__ Asp,
    const float* __restrict__ R, const float* __restrict__ gg,
    const float* __restrict__ bb, const float* __restrict__ logc,
    float* __restrict__ e2o, float* __restrict__ deo, float* __restrict__ keo,
    int KE, int N, int mbase)
{
    constexpr int MF = MT / 32;
    constexpr uint32_t STG = MT * 128 + 16384;
    extern __shared__ char smem[];
    float* smf = (float*)smem;
    const int tid = threadIdx.x, wid = tid >> 5, lane = tid & 31;
    const int m0 = mbase + blockIdx.y * MT, n0 = blockIdx.x * 128;
    const uint32_t sbase = smem_u32(smem);
    const int warp_m = wid & 1, warp_n = wid >> 1;
    const int quad = lane >> 3, l8 = lane & 7;
    const int nstage = KE >> 6;

    float acc[MF][4][4] = {};

    auto load_stage = [&](int s) {
        const uint32_t sA = sbase + (uint32_t)(s & 1) * STG;
        const uint32_t sB = sA + MT * 128;
        const size_t kb = (size_t)s * 128;
#pragma unroll
        for (int j = 0; j < MT / 32; ++j) {
            int idx = tid + 256 * j;
            int row = idx >> 3, ch = idx & 7;
            uint32_t so = row * 128 + ((ch ^ (row & 7)) << 4);
            cp_async16(sA + so, (const char*)A + (size_t)(m0 + row) * (KE * 2) + kb + ch * 16);
        }
#pragma unroll
        for (int j = 0; j < 4; ++j) {
            int idx = tid + 256 * j;
            int row = idx >> 3, ch = idx & 7;
            uint32_t so = row * 128 + ((ch ^ (row & 7)) << 4);
            cp_async16(sB + so, (const char*)Bt + (size_t)(n0 + row) * (KE * 2) + kb + ch * 16);
        }
        asm volatile("cp.async.commit_group;" ::: "memory");
    };

    load_stage(0);
#pragma unroll 1
    for (int s = 0; s < nstage; ++s) {
        if (s + 1 < nstage) {
            load_stage(s + 1);
            asm volatile("cp.async.wait_group 1;" ::: "memory");
        } else {
            asm volatile("cp.async.wait_group 0;" ::: "memory");
        }
        __syncthreads();
        const uint32_t aB = sbase + (uint32_t)(s & 1) * STG;
        const uint32_t bB = aB + MT * 128;
#pragma unroll
        for (int ks = 0; ks < 4; ++ks) {
            uint32_t a[MF][4];
#pragma unroll
            for (int mf = 0; mf < MF; ++mf) {
                int mr = warp_m * (MT / 2) + mf * 16 + (quad & 1) * 8 + l8;
                int kc = ks * 2 + (quad >> 1);
                ldmx4(aB + mr * 128 + ((kc ^ (mr & 7)) << 4),
                      a[mf][0], a[mf][1], a[mf][2], a[mf][3]);
            }
            uint32_t b[2][4];
#pragma unroll
            for (int nh = 0; nh < 2; ++nh) {
                int nr = warp_n * 32 + nh * 16 + (quad >> 1) * 8 + l8;
                int kc = ks * 2 + (quad & 1);
                ldmx4(bB + nr * 128 + ((kc ^ (nr & 7)) << 4),
                      b[nh][0], b[nh][1], b[nh][2], b[nh][3]);
            }
#pragma unroll
            for (int mf = 0; mf < MF; ++mf)
#pragma unroll
                for (int nf = 0; nf < 4; ++nf)
                    mma_fp16(acc[mf][nf], a[mf], b[nf >> 1][(nf & 1) * 2],
                             b[nf >> 1][(nf & 1) * 2 + 1]);
        }
        __syncthreads();
    }

    const int g = lane >> 2, tg = lane & 3;
#pragma unroll
    for (int mf = 0; mf < MF; ++mf)
#pragma unroll
        for (int nf = 0; nf < 4; ++nf) {
            int r0 = warp_m * (MT / 2) + mf * 16 + g;
            int col = warp_n * 32 + nf * 8 + tg * 2;
            *(float2*)&smf[r0 * 132 + col]       = make_float2(acc[mf][nf][0], acc[mf][nf][1]);
            *(float2*)&smf[(r0 + 8) * 132 + col] = make_float2(acc[mf][nf][2], acc[mf][nf][3]);
        }
    __syncthreads();

    float4 b4 = *(const float4*)&bias[n0 + lane * 4];
    const float* b4p = &b4.x;
    constexpr int RW = MT / 8;

    if (EPI == 0) {
#pragma unroll
        for (int it = 0; it < RW; ++it) {
            int r = wid * RW + it;
            int grow = m0 + r;
            float4 v = *(const float4*)&smf[r * 132 + lane * 4];
            float* vp = &v.x;
#pragma unroll
            for (int e = 0; e < 4; ++e) {
                float vv = vp[e] + b4p[e];
                if (ACT == 1) vv = gelu_exact(vv);
                vp[e] = vv;
            }
            if (WF32)
                *(float4*)(C + (size_t)grow * N + n0 + lane * 4) = v;
            if (WSP) {
                size_t base = (size_t)grow * WSP * N;
                int cc = n0 + lane * 4;
                __half* hp = Asp + base + cc;
                split4_store(vp, hp, hp + N);
                if (WSP == 3) pack4_store(vp, hp + 2 * N);
            }
        }
    } else {
        float c_ = 0.f, sc_ = 0.f, maxn = 0.f;
        if (EPI == 2) { curvature(logc, c_, sc_); maxn = (1.0f - 1e-5f) / sc_; }
        float4 g4 = *(const float4*)&gg[lane * 4];
        float4 bt4 = *(const float4*)&bb[lane * 4];
        const float* g4p = &g4.x; const float* bt4p = &bt4.x;
#pragma unroll 1
        for (int it = 0; it < RW; ++it) {
            int r = wid * RW + it;
            int grow = m0 + r;
            float4 v = *(const float4*)&smf[r * 132 + lane * 4];
            float* vp = &v.x;
            float x[4];
            if (R != nullptr) {
                float4 rr = *(const float4*)&R[(size_t)grow * ND + lane * 4];
                const float* rrp = &rr.x;
#pragma unroll
                for (int e = 0; e < 4; ++e) x[e] = vp[e] + b4p[e] + rrp[e];
            } else {
#pragma unroll
                for (int e = 0; e < 4; ++e) x[e] = vp[e] + b4p[e];
            }
            float m = warp_sum(x[0] + x[1] + x[2] + x[3]) * (1.0f / 128.0f);
            float q = 0.f;
#pragma unroll
            for (int e = 0; e < 4; ++e) { x[e] -= m; q += x[e] * x[e]; }
            float var = warp_sum(q) * (1.0f / 128.0f);
            float rstd = rsqrtf(var + 1e-5f);
            float y[4];
#pragma unroll
            for (int e = 0; e < 4; ++e) y[e] = x[e] * rstd * g4p[e] + bt4p[e];

            if (EPI == 1) {
                *(float4*)(C + (size_t)grow * ND + lane * 4) = *(float4*)y;
                size_t base = (size_t)grow * 384;
                __half* hp = Asp + base + lane * 4;
                split4_store(y, hp, hp + 128);
                pack4_store(y, hp + 256);
            } else {
                float n2 = warp_sum(y[0]*y[0] + y[1]*y[1] + y[2]*y[2] + y[3]*y[3]);
                float vn = fmaxf(sqrtf(n2), 1e-10f);
                float kk = tanhf(sc_ * vn * 0.5f) / (sc_ * vn);
                float en = kk * vn;
                float scl = fminf(maxn / fmaxf(en, 1e-6f), 1.0f);
                float ke = kk * scl;
                float ee[4];
#pragma unroll
                for (int e = 0; e < 4; ++e) ee[e] = ke * y[e];
                *(float4*)(C + (size_t)grow * ND + lane * 4) = *(float4*)ee;
                pack4_store(y, Asp + (size_t)grow * 128 + lane * 4);
                if (lane == 0) {
                    float e2 = en * en * scl * scl;
                    e2o[grow] = e2;
                    deo[grow] = 1.0f - c_ * fminf(e2, 1.0f - 1e-5f);
                    keo[grow] = ke;
                }
            }
        }
    }
}

// ---------------- merged head: A persists, sequential z planes --------------
#define DB_OFF  32768
#define DS_OFF  65536
#define DSMEM   (65536 + 64 * 132 * 4)   // 99328

__global__ void __launch_bounds__(256, 2) dual_mma(
    const float* __restrict__ e2v, const float* __restrict__ dev,
    const float* __restrict__ kev, const float* __restrict__ logc,
    float* __restrict__ hyp, float* __restrict__ euc, int mbase)
{
    extern __shared__ char smem[];
    float* smf = (float*)(smem + DS_OFF);
    const int tid = threadIdx.x, wid = tid >> 5, lane = tid & 31;
    const int m0 = mbase + blockIdx.y * 128, n0 = blockIdx.x * 128;
    const char* Ag  = (const char*)g_Ay;
    const char* B1g = (const char*)g_B1e;
    const char* B2g = (const char*)g_B2e;
    const uint32_t sbase = smem_u32(smem);
    const int warp_m = wid & 1, warp_n = wid >> 1;
    const int quad = lane >> 3, l8 = lane & 7;

    auto load_A = [&](int s) {
        const uint32_t sA = sbase + (uint32_t)s * 16384;
        const size_t kb = (size_t)s * 128;
#pragma unroll
        for (int j = 0; j < 4; ++j) {
            int idx = tid + 256 * j;
            int row = idx >> 3, ch = idx & 7;
            uint32_t so = row * 128 + ((ch ^ (row & 7)) << 4);
            cp_async16(sA + so, Ag + (size_t)(m0 + row) * 256 + kb + ch * 16);
        }
    };
    auto load_B = [&](const char* Bg, int s) {
        const uint32_t sB = sbase + DB_OFF + (uint32_t)s * 16384;
        const size_t kb = (size_t)s * 128;
#pragma unroll
        for (int j = 0; j < 4; ++j) {
            int idx = tid + 256 * j;
            int row = idx >> 3, ch = idx & 7;
            uint32_t so = row * 128 + ((ch ^ (row & 7)) << 4);
            cp_async16(sB + so, Bg + (size_t)(n0 + row) * 256 + kb + ch * 16);
        }
    };

    const int gc = n0 + lane * 4;
    const bool ok = gc < NC;
    float c_, sc_; curvature(logc, c_, sc_);
    const float inv2sc = 2.0f / sc_;
    const float slg = -inv2sc * 0.69314718055994531f;
    float p2c[4], dpc[4], ebc[4];
    {
        float4 p2 = *(const float4*)&g_p2[gc];
        float4 dp = *(const float4*)&g_dp[gc];
        float4 eb = *(const float4*)&g_eb[gc];
        p2c[0]=p2.x; p2c[1]=p2.y; p2c[2]=p2.z; p2c[3]=p2.w;
        dpc[0]=dp.x; dpc[1]=dp.y; dpc[2]=dp.z; dpc[3]=dp.w;
        ebc[0]=eb.x; ebc[1]=eb.y; ebc[2]=eb.z; ebc[3]=eb.w;
    }

    float acc[4][4][4];
    const int g = lane >> 2, tg = lane & 3;

    auto mainloop = [&]() {
#pragma unroll
        for (int mf = 0; mf < 4; ++mf)
#pragma unroll
            for (int nf = 0; nf < 4; ++nf)
#pragma unroll
                for (int e = 0; e < 4; ++e) acc[mf][nf][e] = 0.f;
#pragma unroll 1
        for (int s = 0; s < 2; ++s) {
            if (s == 0) asm volatile("cp.async.wait_group 1;" ::: "memory");
            else        asm volatile("cp.async.wait_group 0;" ::: "memory");
            __syncthreads();
            const uint32_t aB = sbase + (uint32_t)s * 16384;
            const uint32_t bB = sbase + DB_OFF + (uint32_t)s * 16384;
#pragma unroll
            for (int ks = 0; ks < 4; ++ks) {
                uint32_t a[4][4];
#pragma unroll
                for (int mf = 0; mf < 4; ++mf) {
                    int mr = warp_m * 64 + mf * 16 + (quad & 1) * 8 + l8;
                    int kc = ks * 2 + (quad >> 1);
                    ldmx4(aB + mr * 128 + ((kc ^ (mr & 7)) << 4),
                          a[mf][0], a[mf][1], a[mf][2], a[mf][3]);
                }
                uint32_t b[2][4];
#pragma unroll
                for (int nh = 0; nh < 2; ++nh) {
                    int nr = warp_n * 32 + nh * 16 + (quad >> 1) * 8 + l8;
                    int kc = ks * 2 + (quad & 1);
                    ldmx4(bB + nr * 128 + ((kc ^ (nr & 7)) << 4),
                          b[nh][0], b[nh][1], b[nh][2], b[nh][3]);
                }
#pragma unroll
                for (int mf = 0; mf < 4; ++mf)
#pragma unroll
                    for (int nf = 0; nf < 4; ++nf)
                        mma_fp16(acc[mf][nf], a[mf], b[nf >> 1][(nf & 1) * 2],
                                 b[nf >> 1][(nf & 1) * 2 + 1]);
            }
            __syncthreads();
        }
    };

    auto epilogue = [&](int z) {
        float* dst = z ? euc : hyp;
#pragma unroll 1
        for (int p = 0; p < 2; ++p) {
            if (warp_m == p) {
#pragma unroll
                for (int mf = 0; mf < 4; ++mf)
#pragma unroll
                    for (int nf = 0; nf < 4; ++nf) {
                        int r0 = mf * 16 + g;
                        int col = warp_n * 32 + nf * 8 + tg * 2;
                        *(float2*)&smf[r0 * 132 + col] =
                            make_float2(acc[mf][nf][0], acc[mf][nf][1]);
                        *(float2*)&smf[(r0 + 8) * 132 + col] =
                            make_float2(acc[mf][nf][2], acc[mf][nf][3]);
                    }
            }
            __syncthreads();
#pragma unroll 2
            for (int it = 0; it < 8; ++it) {
                int r = wid * 8 + it;
                int grow = m0 + p * 64 + r;
                float4 v = *(const float4*)&smf[r * 132 + lane * 4];
                float* vp = &v.x;
                if (z == 0) {
                    float e2r = e2v[grow], der = dev[grow];
                    float m2ke = -2.0f * kev[grow];
#pragma unroll
                    for (int e = 0; e < 4; ++e) {
                        float diff = fmaxf(fmaf(m2ke, vp[e], e2r + p2c[e]), 1e-10f);
                        float den  = fmaxf(der * dpc[e], 1e-6f);
                        float num  = fmaf(2.0f, diff, den);
                        float dist;
                        if (diff >= 32.0f * den) {
                            dist = slg * (__log2f(num) - __log2f(den) + 1.0f);
                        } else {
                            float arg = fmaxf(__fdividef(num, den), 1.0f + 1e-6f);
                            dist = -inv2sc * acoshf(arg);
                        }
                        vp[e] = dist;
                    }
                } else {
                    vp[0] += ebc[0]; vp[1] += ebc[1]; vp[2] += ebc[2]; vp[3] += ebc[3];
                }
                if (ok) __stcs((float4*)(dst + (size_t)grow * NC + gc), v);
            }
            __syncthreads();
        }
    };

    load_A(0); load_B(B1g, 0);
    asm volatile("cp.async.commit_group;" ::: "memory");
    load_A(1); load_B(B1g, 1);
    asm volatile("cp.async.commit_group;" ::: "memory");
    mainloop();
    load_B(B2g, 0);
    asm volatile("cp.async.commit_group;" ::: "memory");
    load_B(B2g, 1);
    asm volatile("cp.async.commit_group;" ::: "memory");
    epilogue(0);
    mainloop();
    epilogue(1);
}

// ------------------------------- launch -------------------------------------
extern "C" void kernel_launch(void* const* d_in, const int* in_sizes, int n_in,
                              void* d_out, int out_size)
{
    const float* x      = (const float*)d_in[0];
    const float* W1     = (const float*)d_in[1];
    const float* b1     = (const float*)d_in[2];
    const float* W2     = (const float*)d_in[3];
    const float* b2     = (const float*)d_in[4];
    const float* in_w   = (const float*)d_in[5];
    const float* in_b   = (const float*)d_in[6];
    const float* out_w  = (const float*)d_in[7];
    const float* out_b  = (const float*)d_in[8];
    const float* fw1    = (const float*)d_in[9];
    const float* fb1    = (const float*)d_in[10];
    const float* fw2    = (const float*)d_in[11];
    const float* fb2    = (const float*)d_in[12];
    const float* g1     = (const float*)d_in[13];
    const float* bt1    = (const float*)d_in[14];
    const float* g2     = (const float*)d_in[15];
    const float* bt2    = (const float*)d_in[16];
    const float* logc   = (const float*)d_in[17];
    const float* protos = (const float*)d_in[18];
    const float* euc_w  = (const float*)d_in[19];
    const float* euc_b  = (const float*)d_in[20];

    float *xs, *e2, *de, *ke, *W2c, *bc;
    __half *xsp, *t1sp, *xssp, *hsp, *W1p, *W2cp, *fw1p, *fw2p, *Ay;
    cudaGetSymbolAddress((void**)&xs,   g_xs);
    cudaGetSymbolAddress((void**)&e2,   g_e2);
    cudaGetSymbolAddress((void**)&de,   g_de);
    cudaGetSymbolAddress((void**)&ke,   g_ke);
    cudaGetSymbolAddress((void**)&W2c,  g_W2c);
    cudaGetSymbolAddress((void**)&bc,   g_bc);
    cudaGetSymbolAddress((void**)&xsp,  g_xsp);
    cudaGetSymbolAddress((void**)&t1sp, g_t1sp);
    cudaGetSymbolAddress((void**)&xssp, g_xssp);
    cudaGetSymbolAddress((void**)&hsp,  g_hsp);
    cudaGetSymbolAddress((void**)&W1p,  g_W1p);
    cudaGetSymbolAddress((void**)&W2cp, g_W2cp);
    cudaGetSymbolAddress((void**)&fw1p, g_fw1p);
    cudaGetSymbolAddress((void**)&fw2p, g_fw2p);
    cudaGetSymbolAddress((void**)&Ay,   g_Ay);

    float* out = (float*)d_out;
    float* hyp = out;
    float* euc = out + (size_t)NB * NC;
    float* emb = out + (size_t)NB * NC * 2;

    static cudaStream_t s2 = nullptr, s3 = nullptr;
    static cudaEvent_t evF = nullptr, evW1 = nullptr, evW = nullptr, evJ = nullptr,
                       evFE1 = nullptr, evFE2 = nullptr;
    if (!s2) {
        cudaStreamCreateWithFlags(&s2, cudaStreamNonBlocking);
        cudaStreamCreateWithFlags(&s3, cudaStreamNonBlocking);
        cudaEventCreateWithFlags(&evF, cudaEventDisableTiming);
        cudaEventCreateWithFlags(&evW1, cudaEventDisableTiming);
        cudaEventCreateWithFlags(&evW, cudaEventDisableTiming);
        cudaEventCreateWithFlags(&evJ, cudaEventDisableTiming);
        cudaEventCreateWithFlags(&evFE1, cudaEventDisableTiming);
        cudaEventCreateWithFlags(&evFE2, cudaEventDisableTiming);
        cudaFuncSetAttribute(dual_mma, cudaFuncAttributeMaxDynamicSharedMemorySize, DSMEM);
        cudaFuncSetAttribute(hgemm<32,1,0,0,2>, cudaFuncAttributeMaxDynamicSharedMemorySize, HSMEM);
        cudaFuncSetAttribute(hgemm<32,0,1,0,0>, cudaFuncAttributeMaxDynamicSharedMemorySize, HSMEM);
        cudaFuncSetAttribute(hgemm<64,1,0,0,2>, cudaFuncAttributeMaxDynamicSharedMemorySize, HSMEM);
        cudaFuncSetAttribute(hgemm<32,0,2,0,0>, cudaFuncAttributeMaxDynamicSharedMemorySize, HSMEM);
    }

    // ---- fork: side stream does all weight/proto preps ----
    cudaEventRecord(evF, 0);
    cudaStreamWaitEvent(s2, evF, 0);
    wprep2<<<dim3(NIN / 32, 256 / 32), 256, 0, s2>>>(W1, W1p, NIN, 256);
    cudaEventRecord(evW1, s2);
    fold_w<<<ND + 1, 128, 0, s2>>>(in_w, out_w, in_b, out_b);
    fold2_w<<<257, 128, 0, s2>>>(W2, b2);
    wprep2<<<dim3(256 / 32, 128 / 32), 256, 0, s2>>>(W2c, W2cp, 256, 128);
    wprep<<<dim3(128 / 32, 512 / 32), 256, 0, s2>>>(fw1, fw1p, 128, 512);
    wprep2<<<dim3(512 / 32, 128 / 32), 256, 0, s2>>>(fw2, fw2p, 512, 128);
    cudaEventRecord(evW, s2);
    proto_prep<<<NC2, 128, 0, s2>>>(protos, logc);
    euc_prep <<<NC2 / 64, 256, 0, s2>>>(euc_w, euc_b);
    cudaEventRecord(evJ, s2);

    // ---- main stream: FE chain for half 1 (rows 0..NH-1) ----
    asplit2<<<NH, 256>>>(x, xsp, NIN, 0);
    cudaStreamWaitEvent(0, evW1, 0);
    hgemm<32,1,0,0,2><<<dim3(2, NH / 32), 256, HSMEM>>>(
        xsp, W1p, b1, nullptr, t1sp, nullptr, nullptr, nullptr, nullptr,
        nullptr, nullptr, nullptr, 2048, 256, 0);
    cudaStreamWaitEvent(0, evW, 0);
    hgemm<32,0,1,0,0><<<dim3(1, NH / 32), 256, HSMEM>>>(
        t1sp, W2cp, bc, xs, xssp, nullptr, g1, bt1, nullptr,
        nullptr, nullptr, nullptr, 512, 128, 0);
    hgemm<64,1,0,0,2><<<dim3(4, NH / 64), 256, HSMEM>>>(
        xssp, fw1p, fb1, nullptr, hsp, nullptr, nullptr, nullptr, nullptr,
        nullptr, nullptr, nullptr, 384, 512, 0);
    hgemm<32,0,2,0,0><<<dim3(1, NH / 32), 256, HSMEM>>>(
        hsp, fw2p, fb2, emb, Ay, xs, g2, bt2, logc,
        e2, de, ke, 1024, 128, 0);
    cudaEventRecord(evFE1, 0);

    // ---- s3: FE chain for half 2 (runs concurrent with head half 1) ----
    cudaStreamWaitEvent(s3, evFE1, 0);
    asplit2<<<NH, 256, 0, s3>>>(x, xsp, NIN, NH);
    hgemm<32,1,0,0,2><<<dim3(2, NH / 32), 256, HSMEM, s3>>>(
        xsp, W1p, b1, nullptr, t1sp, nullptr, nullptr, nullptr, nullptr,
        nullptr, nullptr, nullptr, 2048, 256, NH);
    hgemm<32,0,1,0,0><<<dim3(1, NH / 32), 256, HSMEM, s3>>>(
        t1sp, W2cp, bc, xs, xssp, nullptr, g1, bt1, nullptr,
        nullptr, nullptr, nullptr, 512, 128, NH);
    hgemm<64,1,0,0,2><<<dim3(4, NH / 64), 256, HSMEM, s3>>>(
        xssp, fw1p, fb1, nullptr, hsp, nullptr, nullptr, nullptr, nullptr,
        nullptr, nullptr, nullptr, 384, 512, NH);
    hgemm<32,0,2,0,0><<<dim3(1, NH / 32), 256, HSMEM, s3>>>(
        hsp, fw2p, fb2, emb, Ay, xs, g2, bt2, logc,
        e2, de, ke, 1024, 128, NH);
    cudaEventRecord(evFE2, s3);

    // ---- main: head half 1 (overlaps FE half 2), then head half 2 ----
    cudaStreamWaitEvent(0, evJ, 0);
    dual_mma<<<dim3(NC2 / 128, NH / 128), 256, DSMEM>>>(e2, de, ke, logc, hyp, euc, 0);
    cudaStreamWaitEvent(0, evFE2, 0);
    dual_mma<<<dim3(NC2 / 128, NH / 128), 256, DSMEM>>>(e2, de, ke, logc, hyp, euc, NH);
}

// round 16
// speedup vs baseline: 1.1806x; 1.1806x over previous
#include <cuda_runtime.h>
#include <cuda_fp16.h>
#include <math.h>
#include <stdint.h>

// ---------------------------------------------------------------------------
// B=4096, IN_DIM=1024, D=128, C=10000. seq_len==1 -> attn == v (q,k dead).
// Attention composed: xs = LN(t1 @ [W2@(Wp+I)] + b''), Wp = Wv@out_w.
// mma.sync fp16: x/t1/xs/h all 2-term splits, head 1-term fp16 K=128.
// Head: merged kernel, A persists across planes; z=1 B prefetched under the
// z=0 epilogue. emb = ke*y (row scalar) folds into the hyp epilogue.
// ---------------------------------------------------------------------------

#define NB   4096
#define NIN  1024
#define ND   128
#define NC   10000
#define NC2  10112

// ------------------------- device scratch (no allocs) ----------------------
__device__ float g_xs[NB * ND];
__device__ float g_e2[NB];
__device__ float g_de[NB];
__device__ float g_ke[NB];
__device__ float g_Wp[ND * ND];
__device__ float g_bp[ND];
__device__ float g_W2c[256 * ND];
__device__ float g_bc [ND];
__device__ uint4 g_xsp [NB * 2048 / 8];    // x 2-term
__device__ uint4 g_t1sp[NB * 512  / 8];    // t1 2-term
__device__ uint4 g_xssp[NB * 256  / 8];    // xs 2-term
__device__ uint4 g_hsp [NB * 1024 / 8];    // h 2-term
__device__ uint4 g_W1p [256 * 2048 / 8];   // 2-term
__device__ uint4 g_W2cp[128 * 512  / 8];   // 2-term
__device__ uint4 g_fw1p[512 * 256  / 8];   // 2-term
__device__ uint4 g_fw2p[128 * 1024 / 8];   // 2-term
__device__ uint4 g_Ay [NB  * 128 / 8];
__device__ uint4 g_B1e[NC2 * 128 / 8];
__device__ uint4 g_B2e[NC2 * 128 / 8];
__device__ float g_p2[NC2];
__device__ float g_dp[NC2];
__device__ float g_eb[NC2];

// ------------------------------ helpers ------------------------------------
static __device__ __forceinline__ uint32_t smem_u32(const void* p) {
    uint32_t a;
    asm("{ .reg .u64 t; cvta.to.shared.u64 t, %1; cvt.u32.u64 %0, t; }" : "=r"(a) : "l"(p));
    return a;
}
static __device__ __forceinline__ void cp_async16(uint32_t s, const void* g) {
    asm volatile("cp.async.cg.shared.global [%0], [%1], 16;" :: "r"(s), "l"(g) : "memory");
}
static __device__ __forceinline__ void ldmx4(uint32_t a, uint32_t& r0, uint32_t& r1,
                                             uint32_t& r2, uint32_t& r3) {
    asm volatile("ldmatrix.sync.aligned.m8n8.x4.shared.b16 {%0,%1,%2,%3}, [%4];"
                 : "=r"(r0), "=r"(r1), "=r"(r2), "=r"(r3) : "r"(a));
}
static __device__ __forceinline__ void mma_fp16(float* d, const uint32_t* a,
                                                uint32_t b0, uint32_t b1) {
    asm volatile("mma.sync.aligned.m16n8k16.row.col.f32.f16.f16.f32 "
                 "{%0,%1,%2,%3}, {%4,%5,%6,%7}, {%8,%9}, {%0,%1,%2,%3};"
                 : "+f"(d[0]), "+f"(d[1]), "+f"(d[2]), "+f"(d[3])
                 : "r"(a[0]), "r"(a[1]), "r"(a[2]), "r"(a[3]), "r"(b0), "r"(b1));
}
static __device__ __forceinline__ float gelu_exact(float x) {
    return 0.5f * x * (1.0f + erff(x * 0.70710678118654752440f));
}
static __device__ __forceinline__ float warp_sum(float v) {
#pragma unroll
    for (int o = 16; o > 0; o >>= 1) v += __shfl_xor_sync(0xffffffffu, v, o);
    return v;
}
static __device__ __forceinline__ float block_sum_128(float v) {
    __shared__ float sh[4];
    int lane = threadIdx.x & 31, wid = threadIdx.x >> 5;
    v = warp_sum(v);
    __syncthreads();
    if (lane == 0) sh[wid] = v;
    __syncthreads();
    return sh[0] + sh[1] + sh[2] + sh[3];
}
static __device__ __forceinline__ void curvature(const float* logc, float& c, float& sc) {
    float cc = expf(logc[0]);
    cc = fminf(fmaxf(cc, 1e-4f), 10.0f);
    cc = fmaxf(fabsf(cc), 1e-6f);
    c = cc; sc = sqrtf(cc);
}
static __device__ __forceinline__ void split_hl(float x, __half& h, __half& l) {
    h = __float2half_rn(x);
    l = __float2half_rn(x - __half2float(h));
}
static __device__ __forceinline__ void split4_store(const float* v, __half* hip, __half* lop) {
    __half h[4], l[4];
#pragma unroll
    for (int e = 0; e < 4; ++e) split_hl(v[e], h[e], l[e]);
    __half2 h01 = __halves2half2(h[0], h[1]), h23 = __halves2half2(h[2], h[3]);
    __half2 l01 = __halves2half2(l[0], l[1]), l23 = __halves2half2(l[2], l[3]);
    uint2 ph, pl;
    ph.x = *(uint32_t*)&h01; ph.y = *(uint32_t*)&h23;
    pl.x = *(uint32_t*)&l01; pl.y = *(uint32_t*)&l23;
    *(uint2*)hip = ph;
    *(uint2*)lop = pl;
}
static __device__ __forceinline__ void pack4_store(const float* v, __half* hip) {
    __half h[4];
#pragma unroll
    for (int e = 0; e < 4; ++e) h[e] = __float2half_rn(v[e]);
    __half2 h01 = __halves2half2(h[0], h[1]), h23 = __halves2half2(h[2], h[3]);
    uint2 ph; ph.x = *(uint32_t*)&h01; ph.y = *(uint32_t*)&h23;
    *(uint2*)hip = ph;
}

// ------------------- preps -------------------------------------------------
__global__ void asplit2(const float* __restrict__ X, __half* __restrict__ out, int K)
{
    int row = blockIdx.x;
    const float4* xr = (const float4*)(X + (size_t)row * K);
    __half* o = out + (size_t)row * 2 * K;
    for (int k4 = threadIdx.x; k4 < (K >> 2); k4 += 256) {
        float4 v = xr[k4];
        float* vp = &v.x;
        int k = k4 * 4;
        __half h[4], l[4];
#pragma unroll
        for (int e = 0; e < 4; ++e) split_hl(vp[e], h[e], l[e]);
        __half2 h01 = __halves2half2(h[0], h[1]), h23 = __halves2half2(h[2], h[3]);
        __half2 l01 = __halves2half2(l[0], l[1]), l23 = __halves2half2(l[2], l[3]);
        uint2 ph, pl;
        ph.x = *(uint32_t*)&h01; ph.y = *(uint32_t*)&h23;
        pl.x = *(uint32_t*)&l01; pl.y = *(uint32_t*)&l23;
        *(uint2*)(o + k) = ph;
        *(uint2*)(o + K + k) = pl;
    }
}
__global__ void __launch_bounds__(256) wprep2(const float* __restrict__ W,
                                              __half* __restrict__ out, int K, int N)
{
    __shared__ float t[32][33];
    const int k0 = blockIdx.x * 32, n0 = blockIdx.y * 32;
    const int tx = threadIdx.x & 31, ty = threadIdx.x >> 5;
#pragma unroll
    for (int i = ty; i < 32; i += 8)
        t[i][tx] = W[(size_t)(k0 + i) * N + n0 + tx];
    __syncthreads();
#pragma unroll
    for (int i = ty; i < 32; i += 8) {
        int n = n0 + i, k = k0 + tx;
        __half h = __float2half_rn(t[tx][i]);
        size_t base = (size_t)n * 2 * K;
        out[base + k] = h; out[base + K + k] = h;
    }
}
__global__ void fold_w(const float* __restrict__ in_w, const float* __restrict__ out_w,
                       const float* __restrict__ in_b, const float* __restrict__ out_b)
{
    int j = threadIdx.x;
    if (blockIdx.x < ND) {
        int k = blockIdx.x;
        float s = 0.f;
#pragma unroll 8
        for (int m = 0; m < ND; ++m)
            s = fmaf(in_w[k * 384 + 256 + m], out_w[m * ND + j], s);
        g_Wp[k * ND + j] = s;
    } else {
        float s = out_b[j];
#pragma unroll 8
        for (int m = 0; m < ND; ++m)
            s = fmaf(in_b[256 + m], out_w[m * ND + j], s);
        g_bp[j] = s;
    }
}
__global__ void fold2_w(const float* __restrict__ W2, const float* __restrict__ b2)
{
    int j = threadIdx.x;
    if (blockIdx.x < 256) {
        int k = blockIdx.x;
        float s = W2[k * ND + j];
#pragma unroll 8
        for (int m = 0; m < ND; ++m)
            s = fmaf(W2[k * ND + m], g_Wp[m * ND + j], s);
        g_W2c[k * ND + j] = s;
    } else {
        float s = g_bp[j] + b2[j];
#pragma unroll 8
        for (int m = 0; m < ND; ++m)
            s = fmaf(b2[m], g_Wp[m * ND + j], s);
        g_bc[j] = s;
    }
}
__global__ void proto_prep(const float* __restrict__ P, const float* __restrict__ logc)
{
    int row = blockIdx.x, tid = threadIdx.x;
    float p = (row < NC) ? P[(size_t)row * ND + tid] : 0.0f;
    float n2 = block_sum_128(p * p);
    float c, sc; curvature(logc, c, sc);
    float maxn = (1.0f - 1e-5f) / sc;
    float scl = fminf(maxn / fmaxf(sqrtf(n2), 1e-6f), 1.0f);
    p *= scl;
    __half* B1 = (__half*)g_B1e;
    B1[(size_t)row * 128 + tid] = __float2half_rn(p);
    if (tid == 0) {
        float p2 = n2 * scl * scl;
        g_p2[row] = p2;
        g_dp[row] = 1.0f - c * fminf(p2, 1.0f - 1e-5f);
    }
}
__global__ void __launch_bounds__(256) euc_prep(const float* __restrict__ W,
                                                const float* __restrict__ bias)
{
    __shared__ float tile[128 * 65];
    const int tid = threadIdx.x;
    const int c0 = blockIdx.x * 64;
#pragma unroll
    for (int it = 0; it < 32; ++it) {
        int idx = it * 256 + tid;
        int k = idx >> 6, cc = idx & 63;
        int cls = c0 + cc;
        tile[k * 65 + cc] = (cls < NC) ? W[(size_t)k * NC + cls] : 0.0f;
    }
    __syncthreads();
    const int cc = tid & 63, q = tid >> 6;
    __half* B2 = (__half*)g_B2e;
    const size_t base = (size_t)(c0 + cc) * 128;
#pragma unroll
    for (int j8 = 0; j8 < 4; ++j8) {
        int k = q * 32 + j8 * 8;
        __half2 hp[4];
#pragma unroll
        for (int e = 0; e < 4; ++e)
            hp[e] = __halves2half2(__float2half_rn(tile[(k + 2 * e) * 65 + cc]),
                                   __float2half_rn(tile[(k + 2 * e + 1) * 65 + cc]));
        uint4 pk;
        pk.x = *(uint32_t*)&hp[0]; pk.y = *(uint32_t*)&hp[1];
        pk.z = *(uint32_t*)&hp[2]; pk.w = *(uint32_t*)&hp[3];
        *(uint4*)(B2 + base + k) = pk;
    }
    if (tid < 64) {
        int cls = c0 + tid;
        g_eb[cls] = (cls < NC) ? bias[cls] : 0.0f;
    }
}

// ---------------- tensor GEMM, MT x 128 tile, fused epilogues ---------------
// WSP: 0 = none, 2 = 2-term split out. EPI 0: act+bias; 1: LN; 2: LN+emb.
#define HSMEM 49152

template <int MT, int ACT, int EPI, int WF32, int WSP>
__global__ void __launch_bounds__(256, 2) hgemm(
    const __half* __restrict__ A, const __half* __restrict__ Bt,
    const float* __restrict__ bias,
    float* __restrict__ C, __half* __restrict__ Asp,
    const float* __restrict__ R, const float* __restrict__ gg,
    const float* __restrict__ bb, const float* __restrict__ logc,
    float* __restrict__ e2o, float* __restrict__ deo, float* __restrict__ keo,
    int KE, int N)
{
    constexpr int MF = MT / 32;
    constexpr uint32_t STG = MT * 128 + 16384;
    extern __shared__ char smem[];
    float* smf = (float*)smem;
    const int tid = threadIdx.x, wid = tid >> 5, lane = tid & 31;
    const int m0 = blockIdx.y * MT, n0 = blockIdx.x * 128;
    const uint32_t sbase = smem_u32(smem);
    const int warp_m = wid & 1, warp_n = wid >> 1;
    const int quad = lane >> 3, l8 = lane & 7;
    const int nstage = KE >> 6;

    float acc[MF][4][4] = {};

    auto load_stage = [&](int s) {
        const uint32_t sA = sbase + (uint32_t)(s & 1) * STG;
        const uint32_t sB = sA + MT * 128;
        const size_t kb = (size_t)s * 128;
#pragma unroll
        for (int j = 0; j < MT / 32; ++j) {
            int idx = tid + 256 * j;
            int row = idx >> 3, ch = idx & 7;
            uint32_t so = row * 128 + ((ch ^ (row & 7)) << 4);
            cp_async16(sA + so, (const char*)A + (size_t)(m0 + row) * (KE * 2) + kb + ch * 16);
        }
#pragma unroll
        for (int j = 0; j < 4; ++j) {
            int idx = tid + 256 * j;
            int row = idx >> 3, ch = idx & 7;
            uint32_t so = row * 128 + ((ch ^ (row & 7)) << 4);
            cp_async16(sB + so, (const char*)Bt + (size_t)(n0 + row) * (KE * 2) + kb + ch * 16);
        }
        asm volatile("cp.async.commit_group;" ::: "memory");
    };

    load_stage(0);
#pragma unroll 1
    for (int s = 0; s < nstage; ++s) {
        if (s + 1 < nstage) {
            load_stage(s + 1);
            asm volatile("cp.async.wait_group 1;" ::: "memory");
        } else {
            asm volatile("cp.async.wait_group 0;" ::: "memory");
        }
        __syncthreads();
        const uint32_t aB = sbase + (uint32_t)(s & 1) * STG;
        const uint32_t bB = aB + MT * 128;
#pragma unroll
        for (int ks = 0; ks < 4; ++ks) {
            uint32_t a[MF][4];
#pragma unroll
            for (int mf = 0; mf < MF; ++mf) {
                int mr = warp_m * (MT / 2) + mf * 16 + (quad & 1) * 8 + l8;
                int kc = ks * 2 + (quad >> 1);
                ldmx4(aB + mr * 128 + ((kc ^ (mr & 7)) << 4),
                      a[mf][0], a[mf][1], a[mf][2], a[mf][3]);
            }
            uint32_t b[2][4];
#pragma unroll
            for (int nh = 0; nh < 2; ++nh) {
                int nr = warp_n * 32 + nh * 16 + (quad >> 1) * 8 + l8;
                int kc = ks * 2 + (quad & 1);
                ldmx4(bB + nr * 128 + ((kc ^ (nr & 7)) << 4),
                      b[nh][0], b[nh][1], b[nh][2], b[nh][3]);
            }
#pragma unroll
            for (int mf = 0; mf < MF; ++mf)
#pragma unroll
                for (int nf = 0; nf < 4; ++nf)
                    mma_fp16(acc[mf][nf], a[mf], b[nf >> 1][(nf & 1) * 2],
                             b[nf >> 1][(nf & 1) * 2 + 1]);
        }
        __syncthreads();
    }

    const int g = lane >> 2, tg = lane & 3;
#pragma unroll
    for (int mf = 0; mf < MF; ++mf)
#pragma unroll
        for (int nf = 0; nf < 4; ++nf) {
            int r0 = warp_m * (MT / 2) + mf * 16 + g;
            int col = warp_n * 32 + nf * 8 + tg * 2;
            *(float2*)&smf[r0 * 132 + col]       = make_float2(acc[mf][nf][0], acc[mf][nf][1]);
            *(float2*)&smf[(r0 + 8) * 132 + col] = make_float2(acc[mf][nf][2], acc[mf][nf][3]);
        }
    __syncthreads();

    float4 b4 = *(const float4*)&bias[n0 + lane * 4];
    const float* b4p = &b4.x;
    constexpr int RW = MT / 8;

    if (EPI == 0) {
#pragma unroll
        for (int it = 0; it < RW; ++it) {
            int r = wid * RW + it;
            int grow = m0 + r;
            float4 v = *(const float4*)&smf[r * 132 + lane * 4];
            float* vp = &v.x;
#pragma unroll
            for (int e = 0; e < 4; ++e) {
                float vv = vp[e] + b4p[e];
                if (ACT == 1) vv = gelu_exact(vv);
                vp[e] = vv;
            }
            if (WF32)
                *(float4*)(C + (size_t)grow * N + n0 + lane * 4) = v;
            if (WSP) {
                size_t base = (size_t)grow * 2 * N;
                int cc = n0 + lane * 4;
                __half* hp = Asp + base + cc;
                split4_store(vp, hp, hp + N);
            }
        }
    } else {
        float c_ = 0.f, sc_ = 0.f, maxn = 0.f;
        if (EPI == 2) { curvature(logc, c_, sc_); maxn = (1.0f - 1e-5f) / sc_; }
        float4 g4 = *(const float4*)&gg[lane * 4];
        float4 bt4 = *(const float4*)&bb[lane * 4];
        const float* g4p = &g4.x; const float* bt4p = &bt4.x;
#pragma unroll 1
        for (int it = 0; it < RW; ++it) {
            int r = wid * RW + it;
            int grow = m0 + r;
            float4 v = *(const float4*)&smf[r * 132 + lane * 4];
            float* vp = &v.x;
            float x[4];
            if (R != nullptr) {
                float4 rr = *(const float4*)&R[(size_t)grow * ND + lane * 4];
                const float* rrp = &rr.x;
#pragma unroll
                for (int e = 0; e < 4; ++e) x[e] = vp[e] + b4p[e] + rrp[e];
            } else {
#pragma unroll
                for (int e = 0; e < 4; ++e) x[e] = vp[e] + b4p[e];
            }
            float m = warp_sum(x[0] + x[1] + x[2] + x[3]) * (1.0f / 128.0f);
            float q = 0.f;
#pragma unroll
            for (int e = 0; e < 4; ++e) { x[e] -= m; q += x[e] * x[e]; }
            float var = warp_sum(q) * (1.0f / 128.0f);
            float rstd = rsqrtf(var + 1e-5f);
            float y[4];
#pragma unroll
            for (int e = 0; e < 4; ++e) y[e] = x[e] * rstd * g4p[e] + bt4p[e];

            if (EPI == 1) {
                *(float4*)(C + (size_t)grow * ND + lane * 4) = *(float4*)y;
                size_t base = (size_t)grow * 256;
                __half* hp = Asp + base + lane * 4;
                split4_store(y, hp, hp + 128);
            } else {
                float n2 = warp_sum(y[0]*y[0] + y[1]*y[1] + y[2]*y[2] + y[3]*y[3]);
                float vn = fmaxf(sqrtf(n2), 1e-10f);
                float kk = tanhf(sc_ * vn * 0.5f) / (sc_ * vn);
                float en = kk * vn;
                float scl = fminf(maxn / fmaxf(en, 1e-6f), 1.0f);
                float ke = kk * scl;
                float ee[4];
#pragma unroll
                for (int e = 0; e < 4; ++e) ee[e] = ke * y[e];
                *(float4*)(C + (size_t)grow * ND + lane * 4) = *(float4*)ee;
                pack4_store(y, Asp + (size_t)grow * 128 + lane * 4);
                if (lane == 0) {
                    float e2 = en * en * scl * scl;
                    e2o[grow] = e2;
                    deo[grow] = 1.0f - c_ * fminf(e2, 1.0f - 1e-5f);
                    keo[grow] = ke;
                }
            }
        }
    }
}

// ---------------- merged head: A persists, sequential z planes --------------
#define DB_OFF  32768
#define DS_OFF  65536
#define DSMEM   (65536 + 64 * 132 * 4)   // 99328

__global__ void __launch_bounds__(256, 2) dual_mma(
    const float* __restrict__ e2v, const float* __restrict__ dev,
    const float* __restrict__ kev, const float* __restrict__ logc,
    float* __restrict__ hyp, float* __restrict__ euc)
{
    extern __shared__ char smem[];
    float* smf = (float*)(smem + DS_OFF);
    const int tid = threadIdx.x, wid = tid >> 5, lane = tid & 31;
    const int m0 = blockIdx.y * 128, n0 = blockIdx.x * 128;
    const char* Ag  = (const char*)g_Ay;
    const char* B1g = (const char*)g_B1e;
    const char* B2g = (const char*)g_B2e;
    const uint32_t sbase = smem_u32(smem);
    const int warp_m = wid & 1, warp_n = wid >> 1;
    const int quad = lane >> 3, l8 = lane & 7;

    auto load_A = [&](int s) {
        const uint32_t sA = sbase + (uint32_t)s * 16384;
        const size_t kb = (size_t)s * 128;
#pragma unroll
        for (int j = 0; j < 4; ++j) {
            int idx = tid + 256 * j;
            int row = idx >> 3, ch = idx & 7;
            uint32_t so = row * 128 + ((ch ^ (row & 7)) << 4);
            cp_async16(sA + so, Ag + (size_t)(m0 + row) * 256 + kb + ch * 16);
        }
    };
    auto load_B = [&](const char* Bg, int s) {
        const uint32_t sB = sbase + DB_OFF + (uint32_t)s * 16384;
        const size_t kb = (size_t)s * 128;
#pragma unroll
        for (int j = 0; j < 4; ++j) {
            int idx = tid + 256 * j;
            int row = idx >> 3, ch = idx & 7;
            uint32_t so = row * 128 + ((ch ^ (row & 7)) << 4);
            cp_async16(sB + so, Bg + (size_t)(n0 + row) * 256 + kb + ch * 16);
        }
    };

    const int gc = n0 + lane * 4;
    const bool ok = gc < NC;
    float c_, sc_; curvature(logc, c_, sc_);
    const float inv2sc = 2.0f / sc_;
    const float slg = -inv2sc * 0.69314718055994531f;
    float p2c[4], dpc[4], ebc[4];
    {
        float4 p2 = *(const float4*)&g_p2[gc];
        float4 dp = *(const float4*)&g_dp[gc];
        float4 eb = *(const float4*)&g_eb[gc];
        p2c[0]=p2.x; p2c[1]=p2.y; p2c[2]=p2.z; p2c[3]=p2.w;
        dpc[0]=dp.x; dpc[1]=dp.y; dpc[2]=dp.z; dpc[3]=dp.w;
        ebc[0]=eb.x; ebc[1]=eb.y; ebc[2]=eb.z; ebc[3]=eb.w;
    }

    float acc[4][4][4];
    const int g = lane >> 2, tg = lane & 3;

    auto mainloop = [&]() {
#pragma unroll
        for (int mf = 0; mf < 4; ++mf)
#pragma unroll
            for (int nf = 0; nf < 4; ++nf)
#pragma unroll
                for (int e = 0; e < 4; ++e) acc[mf][nf][e] = 0.f;
#pragma unroll 1
        for (int s = 0; s < 2; ++s) {
            if (s == 0) asm volatile("cp.async.wait_group 1;" ::: "memory");
            else        asm volatile("cp.async.wait_group 0;" ::: "memory");
            __syncthreads();
            const uint32_t aB = sbase + (uint32_t)s * 16384;
            const uint32_t bB = sbase + DB_OFF + (uint32_t)s * 16384;
#pragma unroll
            for (int ks = 0; ks < 4; ++ks) {
                uint32_t a[4][4];
#pragma unroll
                for (int mf = 0; mf < 4; ++mf) {
                    int mr = warp_m * 64 + mf * 16 + (quad & 1) * 8 + l8;
                    int kc = ks * 2 + (quad >> 1);
                    ldmx4(aB + mr * 128 + ((kc ^ (mr & 7)) << 4),
                          a[mf][0], a[mf][1], a[mf][2], a[mf][3]);
                }
                uint32_t b[2][4];
#pragma unroll
                for (int nh = 0; nh < 2; ++nh) {
                    int nr = warp_n * 32 + nh * 16 + (quad >> 1) * 8 + l8;
                    int kc = ks * 2 + (quad & 1);
                    ldmx4(bB + nr * 128 + ((kc ^ (nr & 7)) << 4),
                          b[nh][0], b[nh][1], b[nh][2], b[nh][3]);
                }
#pragma unroll
                for (int mf = 0; mf < 4; ++mf)
#pragma unroll
                    for (int nf = 0; nf < 4; ++nf)
                        mma_fp16(acc[mf][nf], a[mf], b[nf >> 1][(nf & 1) * 2],
                                 b[nf >> 1][(nf & 1) * 2 + 1]);
            }
            __syncthreads();
        }
    };

    auto epilogue = [&](int z) {
        float* dst = z ? euc : hyp;
#pragma unroll 1
        for (int p = 0; p < 2; ++p) {
            if (warp_m == p) {
#pragma unroll
                for (int mf = 0; mf < 4; ++mf)
#pragma unroll
                    for (int nf = 0; nf < 4; ++nf) {
                        int r0 = mf * 16 + g;
                        int col = warp_n * 32 + nf * 8 + tg * 2;
                        *(float2*)&smf[r0 * 132 + col] =
                            make_float2(acc[mf][nf][0], acc[mf][nf][1]);
                        *(float2*)&smf[(r0 + 8) * 132 + col] =
                            make_float2(acc[mf][nf][2], acc[mf][nf][3]);
                    }
            }
            __syncthreads();
#pragma unroll 2
            for (int it = 0; it < 8; ++it) {
                int r = wid * 8 + it;
                int grow = m0 + p * 64 + r;
                float4 v = *(const float4*)&smf[r * 132 + lane * 4];
                float* vp = &v.x;
                if (z == 0) {
                    float e2r = e2v[grow], der = dev[grow];
                    float m2ke = -2.0f * kev[grow];
#pragma unroll
                    for (int e = 0; e < 4; ++e) {
                        float diff = fmaxf(fmaf(m2ke, vp[e], e2r + p2c[e]), 1e-10f);
                        float den  = fmaxf(der * dpc[e], 1e-6f);
                        float num  = fmaf(2.0f, diff, den);
                        float dist;
                        if (diff >= 32.0f * den) {
                            dist = slg * (__log2f(num) - __log2f(den) + 1.0f);
                        } else {
                            float arg = fmaxf(__fdividef(num, den), 1.0f + 1e-6f);
                            dist = -inv2sc * acoshf(arg);
                        }
                        vp[e] = dist;
                    }
                } else {
                    vp[0] += ebc[0]; vp[1] += ebc[1]; vp[2] += ebc[2]; vp[3] += ebc[3];
                }
                if (ok) __stcs((float4*)(dst + (size_t)grow * NC + gc), v);
            }
            __syncthreads();
        }
    };

    load_A(0); load_B(B1g, 0);
    asm volatile("cp.async.commit_group;" ::: "memory");
    load_A(1); load_B(B1g, 1);
    asm volatile("cp.async.commit_group;" ::: "memory");
    mainloop();
    load_B(B2g, 0);
    asm volatile("cp.async.commit_group;" ::: "memory");
    load_B(B2g, 1);
    asm volatile("cp.async.commit_group;" ::: "memory");
    epilogue(0);
    mainloop();
    epilogue(1);
}

// ------------------------------- launch -------------------------------------
extern "C" void kernel_launch(void* const* d_in, const int* in_sizes, int n_in,
                              void* d_out, int out_size)
{
    const float* x      = (const float*)d_in[0];
    const float* W1     = (const float*)d_in[1];
    const float* b1     = (const float*)d_in[2];
    const float* W2     = (const float*)d_in[3];
    const float* b2     = (const float*)d_in[4];
    const float* in_w   = (const float*)d_in[5];
    const float* in_b   = (const float*)d_in[6];
    const float* out_w  = (const float*)d_in[7];
    const float* out_b  = (const float*)d_in[8];
    const float* fw1    = (const float*)d_in[9];
    const float* fb1    = (const float*)d_in[10];
    const float* fw2    = (const float*)d_in[11];
    const float* fb2    = (const float*)d_in[12];
    const float* g1     = (const float*)d_in[13];
    const float* bt1    = (const float*)d_in[14];
    const float* g2     = (const float*)d_in[15];
    const float* bt2    = (const float*)d_in[16];
    const float* logc   = (const float*)d_in[17];
    const float* protos = (const float*)d_in[18];
    const float* euc_w  = (const float*)d_in[19];
    const float* euc_b  = (const float*)d_in[20];

    float *xs, *e2, *de, *ke, *W2c, *bc;
    __half *xsp, *t1sp, *xssp, *hsp, *W1p, *W2cp, *fw1p, *fw2p, *Ay;
    cudaGetSymbolAddress((void**)&xs,   g_xs);
    cudaGetSymbolAddress((void**)&e2,   g_e2);
    cudaGetSymbolAddress((void**)&de,   g_de);
    cudaGetSymbolAddress((void**)&ke,   g_ke);
    cudaGetSymbolAddress((void**)&W2c,  g_W2c);
    cudaGetSymbolAddress((void**)&bc,   g_bc);
    cudaGetSymbolAddress((void**)&xsp,  g_xsp);
    cudaGetSymbolAddress((void**)&t1sp, g_t1sp);
    cudaGetSymbolAddress((void**)&xssp, g_xssp);
    cudaGetSymbolAddress((void**)&hsp,  g_hsp);
    cudaGetSymbolAddress((void**)&W1p,  g_W1p);
    cudaGetSymbolAddress((void**)&W2cp, g_W2cp);
    cudaGetSymbolAddress((void**)&fw1p, g_fw1p);
    cudaGetSymbolAddress((void**)&fw2p, g_fw2p);
    cudaGetSymbolAddress((void**)&Ay,   g_Ay);

    float* out = (float*)d_out;
    float* hyp = out;
    float* euc = out + (size_t)NB * NC;
    float* emb = out + (size_t)NB * NC * 2;

    static cudaStream_t s2 = nullptr;
    static cudaEvent_t evF = nullptr, evW1 = nullptr, evW = nullptr, evJ = nullptr;
    if (!s2) {
        cudaStreamCreateWithFlags(&s2, cudaStreamNonBlocking);
        cudaEventCreateWithFlags(&evF, cudaEventDisableTiming);
        cudaEventCreateWithFlags(&evW1, cudaEventDisableTiming);
        cudaEventCreateWithFlags(&evW, cudaEventDisableTiming);
        cudaEventCreateWithFlags(&evJ, cudaEventDisableTiming);
        cudaFuncSetAttribute(dual_mma, cudaFuncAttributeMaxDynamicSharedMemorySize, DSMEM);
        cudaFuncSetAttribute(hgemm<32,1,0,0,2>, cudaFuncAttributeMaxDynamicSharedMemorySize, HSMEM);
        cudaFuncSetAttribute(hgemm<32,0,1,0,0>, cudaFuncAttributeMaxDynamicSharedMemorySize, HSMEM);
        cudaFuncSetAttribute(hgemm<64,1,0,0,2>, cudaFuncAttributeMaxDynamicSharedMemorySize, HSMEM);
        cudaFuncSetAttribute(hgemm<32,0,2,0,0>, cudaFuncAttributeMaxDynamicSharedMemorySize, HSMEM);
    }

    // ---- fork: side stream does all weight/proto preps ----
    cudaEventRecord(evF, 0);
    cudaStreamWaitEvent(s2, evF, 0);
    wprep2<<<dim3(NIN / 32, 256 / 32), 256, 0, s2>>>(W1, W1p, NIN, 256);
    cudaEventRecord(evW1, s2);
    fold_w<<<ND + 1, 128, 0, s2>>>(in_w, out_w, in_b, out_b);
    fold2_w<<<257, 128, 0, s2>>>(W2, b2);
    wprep2<<<dim3(256 / 32, 128 / 32), 256, 0, s2>>>(W2c, W2cp, 256, 128);
    wprep2<<<dim3(128 / 32, 512 / 32), 256, 0, s2>>>(fw1, fw1p, 128, 512);
    wprep2<<<dim3(512 / 32, 128 / 32), 256, 0, s2>>>(fw2, fw2p, 512, 128);
    cudaEventRecord(evW, s2);
    proto_prep<<<NC2, 128, 0, s2>>>(protos, logc);
    euc_prep <<<NC2 / 64, 256, 0, s2>>>(euc_w, euc_b);
    cudaEventRecord(evJ, s2);

    // ---- main stream: activation split + composed front-end chain ----
    asplit2<<<NB, 256>>>(x, xsp, NIN);
    cudaStreamWaitEvent(0, evW1, 0);
    hgemm<32,1,0,0,2><<<dim3(2, NB / 32), 256, HSMEM>>>(
        xsp, W1p, b1, nullptr, t1sp, nullptr, nullptr, nullptr, nullptr,
        nullptr, nullptr, nullptr, 2048, 256);
    cudaStreamWaitEvent(0, evW, 0);
    hgemm<32,0,1,0,0><<<dim3(1, NB / 32), 256, HSMEM>>>(
        t1sp, W2cp, bc, xs, xssp, nullptr, g1, bt1, nullptr,
        nullptr, nullptr, nullptr, 512, 128);
    hgemm<64,1,0,0,2><<<dim3(4, NB / 64), 256, HSMEM>>>(
        xssp, fw1p, fb1, nullptr, hsp, nullptr, nullptr, nullptr, nullptr,
        nullptr, nullptr, nullptr, 256, 512);
    hgemm<32,0,2,0,0><<<dim3(1, NB / 32), 256, HSMEM>>>(
        hsp, fw2p, fb2, emb, Ay, xs, g2, bt2, logc,
        e2, de, ke, 1024, 128);

    // ---- join, then merged head ----
    cudaStreamWaitEvent(0, evJ, 0);
    dual_mma<<<dim3(NC2 / 128, NB / 128), 256, DSMEM>>>(e2, de, ke, logc, hyp, euc);
}

// round 17
// speedup vs baseline: 1.1942x; 1.0116x over previous
#include <cuda_runtime.h>
#include <cuda_fp16.h>
#include <math.h>
#include <stdint.h>

// ---------------------------------------------------------------------------
// B=4096, IN_DIM=1024, D=128, C=10000. seq_len==1 -> attn == v (q,k dead).
// Attention composed: xs = LN(t1 @ [W2@(Wp+I)] + b''), Wp = Wv@out_w.
// mma.sync fp16: x/t1/xs/h 2-term splits, head 1-term fp16 K=128.
// hgemm1 fuses the x hi/lo split into its A-loader (no asplit kernel).
// Head: merged kernel, A persists across planes; z=1 B prefetched under the
// z=0 epilogue. emb = ke*y (row scalar) folds into the hyp epilogue.
// ---------------------------------------------------------------------------

#define NB   4096
#define NIN  1024
#define ND   128
#define NC   10000
#define NC2  10112

// ------------------------- device scratch (no allocs) ----------------------
__device__ float g_xs[NB * ND];
__device__ float g_e2[NB];
__device__ float g_de[NB];
__device__ float g_ke[NB];
__device__ float g_Wp[ND * ND];
__device__ float g_bp[ND];
__device__ float g_W2c[256 * ND];
__device__ float g_bc [ND];
__device__ uint4 g_t1sp[NB * 512  / 8];    // t1 2-term
__device__ uint4 g_xssp[NB * 256  / 8];    // xs 2-term
__device__ uint4 g_hsp [NB * 1024 / 8];    // h 2-term
__device__ uint4 g_W1p [256 * 2048 / 8];   // 2-term
__device__ uint4 g_W2cp[128 * 512  / 8];   // 2-term
__device__ uint4 g_fw1p[512 * 256  / 8];   // 2-term
__device__ uint4 g_fw2p[128 * 1024 / 8];   // 2-term
__device__ uint4 g_Ay [NB  * 128 / 8];
__device__ uint4 g_B1e[NC2 * 128 / 8];
__device__ uint4 g_B2e[NC2 * 128 / 8];
__device__ float g_p2[NC2];
__device__ float g_dp[NC2];
__device__ float g_eb[NC2];

// ------------------------------ helpers ------------------------------------
static __device__ __forceinline__ uint32_t smem_u32(const void* p) {
    uint32_t a;
    asm("{ .reg .u64 t; cvta.to.shared.u64 t, %1; cvt.u32.u64 %0, t; }" : "=r"(a) : "l"(p));
    return a;
}
static __device__ __forceinline__ void cp_async16(uint32_t s, const void* g) {
    asm volatile("cp.async.cg.shared.global [%0], [%1], 16;" :: "r"(s), "l"(g) : "memory");
}
static __device__ __forceinline__ void ldmx4(uint32_t a, uint32_t& r0, uint32_t& r1,
                                             uint32_t& r2, uint32_t& r3) {
    asm volatile("ldmatrix.sync.aligned.m8n8.x4.shared.b16 {%0,%1,%2,%3}, [%4];"
                 : "=r"(r0), "=r"(r1), "=r"(r2), "=r"(r3) : "r"(a));
}
static __device__ __forceinline__ void mma_fp16(float* d, const uint32_t* a,
                                                uint32_t b0, uint32_t b1) {
    asm volatile("mma.sync.aligned.m16n8k16.row.col.f32.f16.f16.f32 "
                 "{%0,%1,%2,%3}, {%4,%5,%6,%7}, {%8,%9}, {%0,%1,%2,%3};"
                 : "+f"(d[0]), "+f"(d[1]), "+f"(d[2]), "+f"(d[3])
                 : "r"(a[0]), "r"(a[1]), "r"(a[2]), "r"(a[3]), "r"(b0), "r"(b1));
}
static __device__ __forceinline__ float gelu_exact(float x) {
    return 0.5f * x * (1.0f + erff(x * 0.70710678118654752440f));
}
static __device__ __forceinline__ float warp_sum(float v) {
#pragma unroll
    for (int o = 16; o > 0; o >>= 1) v += __shfl_xor_sync(0xffffffffu, v, o);
    return v;
}
static __device__ __forceinline__ float block_sum_128(float v) {
    __shared__ float sh[4];
    int lane = threadIdx.x & 31, wid = threadIdx.x >> 5;
    v = warp_sum(v);
    __syncthreads();
    if (lane == 0) sh[wid] = v;
    __syncthreads();
    return sh[0] + sh[1] + sh[2] + sh[3];
}
static __device__ __forceinline__ void curvature(const float* logc, float& c, float& sc) {
    float cc = expf(logc[0]);
    cc = fminf(fmaxf(cc, 1e-4f), 10.0f);
    cc = fmaxf(fabsf(cc), 1e-6f);
    c = cc; sc = sqrtf(cc);
}
static __device__ __forceinline__ void split_hl(float x, __half& h, __half& l) {
    h = __float2half_rn(x);
    l = __float2half_rn(x - __half2float(h));
}
static __device__ __forceinline__ void split4_store(const float* v, __half* hip, __half* lop) {
    __half h[4], l[4];
#pragma unroll
    for (int e = 0; e < 4; ++e) split_hl(v[e], h[e], l[e]);
    __half2 h01 = __halves2half2(h[0], h[1]), h23 = __halves2half2(h[2], h[3]);
    __half2 l01 = __halves2half2(l[0], l[1]), l23 = __halves2half2(l[2], l[3]);
    uint2 ph, pl;
    ph.x = *(uint32_t*)&h01; ph.y = *(uint32_t*)&h23;
    pl.x = *(uint32_t*)&l01; pl.y = *(uint32_t*)&l23;
    *(uint2*)hip = ph;
    *(uint2*)lop = pl;
}
static __device__ __forceinline__ void pack4_store(const float* v, __half* hip) {
    __half h[4];
#pragma unroll
    for (int e = 0; e < 4; ++e) h[e] = __float2half_rn(v[e]);
    __half2 h01 = __halves2half2(h[0], h[1]), h23 = __halves2half2(h[2], h[3]);
    uint2 ph; ph.x = *(uint32_t*)&h01; ph.y = *(uint32_t*)&h23;
    *(uint2*)hip = ph;
}

// ------------------- preps -------------------------------------------------
__global__ void __launch_bounds__(256) wprep2(const float* __restrict__ W,
                                              __half* __restrict__ out, int K, int N)
{
    __shared__ float t[32][33];
    const int k0 = blockIdx.x * 32, n0 = blockIdx.y * 32;
    const int tx = threadIdx.x & 31, ty = threadIdx.x >> 5;
#pragma unroll
    for (int i = ty; i < 32; i += 8)
        t[i][tx] = W[(size_t)(k0 + i) * N + n0 + tx];
    __syncthreads();
#pragma unroll
    for (int i = ty; i < 32; i += 8) {
        int n = n0 + i, k = k0 + tx;
        __half h = __float2half_rn(t[tx][i]);
        size_t base = (size_t)n * 2 * K;
        out[base + k] = h; out[base + K + k] = h;
    }
}
__global__ void fold_w(const float* __restrict__ in_w, const float* __restrict__ out_w,
                       const float* __restrict__ in_b, const float* __restrict__ out_b)
{
    int j = threadIdx.x;
    if (blockIdx.x < ND) {
        int k = blockIdx.x;
        float s = 0.f;
#pragma unroll 8
        for (int m = 0; m < ND; ++m)
            s = fmaf(in_w[k * 384 + 256 + m], out_w[m * ND + j], s);
        g_Wp[k * ND + j] = s;
    } else {
        float s = out_b[j];
#pragma unroll 8
        for (int m = 0; m < ND; ++m)
            s = fmaf(in_b[256 + m], out_w[m * ND + j], s);
        g_bp[j] = s;
    }
}
__global__ void fold2_w(const float* __restrict__ W2, const float* __restrict__ b2)
{
    int j = threadIdx.x;
    if (blockIdx.x < 256) {
        int k = blockIdx.x;
        float s = W2[k * ND + j];
#pragma unroll 8
        for (int m = 0; m < ND; ++m)
            s = fmaf(W2[k * ND + m], g_Wp[m * ND + j], s);
        g_W2c[k * ND + j] = s;
    } else {
        float s = g_bp[j] + b2[j];
#pragma unroll 8
        for (int m = 0; m < ND; ++m)
            s = fmaf(b2[m], g_Wp[m * ND + j], s);
        g_bc[j] = s;
    }
}
__global__ void proto_prep(const float* __restrict__ P, const float* __restrict__ logc)
{
    int row = blockIdx.x, tid = threadIdx.x;
    float p = (row < NC) ? P[(size_t)row * ND + tid] : 0.0f;
    float n2 = block_sum_128(p * p);
    float c, sc; curvature(logc, c, sc);
    float maxn = (1.0f - 1e-5f) / sc;
    float scl = fminf(maxn / fmaxf(sqrtf(n2), 1e-6f), 1.0f);
    p *= scl;
    __half* B1 = (__half*)g_B1e;
    B1[(size_t)row * 128 + tid] = __float2half_rn(p);
    if (tid == 0) {
        float p2 = n2 * scl * scl;
        g_p2[row] = p2;
        g_dp[row] = 1.0f - c * fminf(p2, 1.0f - 1e-5f);
    }
}
__global__ void __launch_bounds__(256) euc_prep(const float* __restrict__ W,
                                                const float* __restrict__ bias)
{
    __shared__ float tile[128 * 65];
    const int tid = threadIdx.x;
    const int c0 = blockIdx.x * 64;
#pragma unroll
    for (int it = 0; it < 32; ++it) {
        int idx = it * 256 + tid;
        int k = idx >> 6, cc = idx & 63;
        int cls = c0 + cc;
        tile[k * 65 + cc] = (cls < NC) ? W[(size_t)k * NC + cls] : 0.0f;
    }
    __syncthreads();
    const int cc = tid & 63, q = tid >> 6;
    __half* B2 = (__half*)g_B2e;
    const size_t base = (size_t)(c0 + cc) * 128;
#pragma unroll
    for (int j8 = 0; j8 < 4; ++j8) {
        int k = q * 32 + j8 * 8;
        __half2 hp[4];
#pragma unroll
        for (int e = 0; e < 4; ++e)
            hp[e] = __halves2half2(__float2half_rn(tile[(k + 2 * e) * 65 + cc]),
                                   __float2half_rn(tile[(k + 2 * e + 1) * 65 + cc]));
        uint4 pk;
        pk.x = *(uint32_t*)&hp[0]; pk.y = *(uint32_t*)&hp[1];
        pk.z = *(uint32_t*)&hp[2]; pk.w = *(uint32_t*)&hp[3];
        *(uint4*)(B2 + base + k) = pk;
    }
    if (tid < 64) {
        int cls = c0 + tid;
        g_eb[cls] = (cls < NC) ? bias[cls] : 0.0f;
    }
}

// ---------------- tensor GEMM, MT x 128 tile, fused epilogues ---------------
// WSP: 0 = none, 2 = 2-term split out. EPI 0: act+bias; 1: LN; 2: LN+emb.
// XF32: A operand is raw fp32 (Axf); loader converts hi/lo split in-kernel
//       (logical KE = 2*Kraw; stages < Kraw/64 are hi, rest are lo). MT must be 32.
#define HSMEM 49152

template <int MT, int ACT, int EPI, int WF32, int WSP, int XF32>
__global__ void __launch_bounds__(256, 2) hgemm(
    const __half* __restrict__ A, const float* __restrict__ Axf,
    const __half* __restrict__ Bt,
    const float* __restrict__ bias,
    float* __restrict__ C, __half* __restrict__ Asp,
    const float* __restrict__ R, const float* __restrict__ gg,
    const float* __restrict__ bb, const float* __restrict__ logc,
    float* __restrict__ e2o, float* __restrict__ deo, float* __restrict__ keo,
    int KE, int N)
{
    constexpr int MF = MT / 32;
    constexpr uint32_t STG = MT * 128 + 16384;
    extern __shared__ char smem[];
    float* smf = (float*)smem;
    const int tid = threadIdx.x, wid = tid >> 5, lane = tid & 31;
    const int m0 = blockIdx.y * MT, n0 = blockIdx.x * 128;
    const uint32_t sbase = smem_u32(smem);
    const int warp_m = wid & 1, warp_n = wid >> 1;
    const int quad = lane >> 3, l8 = lane & 7;
    const int nstage = KE >> 6;

    float acc[MF][4][4] = {};

    auto load_stage = [&](int s) {
        const uint32_t sA = sbase + (uint32_t)(s & 1) * STG;
        const uint32_t sB = sA + MT * 128;
        const size_t kb = (size_t)s * 128;
        if (XF32) {
            // MT == 32: 256 chunks of 16B, one per thread. Raw K = KE/2 floats.
            int row = tid >> 3, ch = tid & 7;
            uint32_t so = row * 128 + ((ch ^ (row & 7)) << 4);
            int kh = s * 64 + ch * 8;          // half index in logical row
            int kraw = (kh < (KE >> 1)) ? kh : kh - (KE >> 1);
            const float4* src = (const float4*)(Axf + (size_t)(m0 + row) * (KE >> 1) + kraw);
            float4 v0 = src[0], v1 = src[1];
            float vv[8] = {v0.x, v0.y, v0.z, v0.w, v1.x, v1.y, v1.z, v1.w};
            __half hh[8];
            if (kh < (KE >> 1)) {
#pragma unroll
                for (int e = 0; e < 8; ++e) hh[e] = __float2half_rn(vv[e]);
            } else {
#pragma unroll
                for (int e = 0; e < 8; ++e) {
                    __half hc = __float2half_rn(vv[e]);
                    hh[e] = __float2half_rn(vv[e] - __half2float(hc));
                }
            }
            uint4 pk;
            __half2* pp = (__half2*)&pk;
            pp[0] = __halves2half2(hh[0], hh[1]);
            pp[1] = __halves2half2(hh[2], hh[3]);
            pp[2] = __halves2half2(hh[4], hh[5]);
            pp[3] = __halves2half2(hh[6], hh[7]);
            *(uint4*)(smem + (uint32_t)(s & 1) * STG + so) = pk;
        } else {
#pragma unroll
            for (int j = 0; j < MT / 32; ++j) {
                int idx = tid + 256 * j;
                int row = idx >> 3, ch = idx & 7;
                uint32_t so = row * 128 + ((ch ^ (row & 7)) << 4);
                cp_async16(sA + so, (const char*)A + (size_t)(m0 + row) * (KE * 2) + kb + ch * 16);
            }
        }
#pragma unroll
        for (int j = 0; j < 4; ++j) {
            int idx = tid + 256 * j;
            int row = idx >> 3, ch = idx & 7;
            uint32_t so = row * 128 + ((ch ^ (row & 7)) << 4);
            cp_async16(sB + so, (const char*)Bt + (size_t)(n0 + row) * (KE * 2) + kb + ch * 16);
        }
        asm volatile("cp.async.commit_group;" ::: "memory");
    };

    load_stage(0);
#pragma unroll 1
    for (int s = 0; s < nstage; ++s) {
        if (s + 1 < nstage) {
            load_stage(s + 1);
            asm volatile("cp.async.wait_group 1;" ::: "memory");
        } else {
            asm volatile("cp.async.wait_group 0;" ::: "memory");
        }
        __syncthreads();
        const uint32_t aB = sbase + (uint32_t)(s & 1) * STG;
        const uint32_t bB = aB + MT * 128;
#pragma unroll
        for (int ks = 0; ks < 4; ++ks) {
            uint32_t a[MF][4];
#pragma unroll
            for (int mf = 0; mf < MF; ++mf) {
                int mr = warp_m * (MT / 2) + mf * 16 + (quad & 1) * 8 + l8;
                int kc = ks * 2 + (quad >> 1);
                ldmx4(aB + mr * 128 + ((kc ^ (mr & 7)) << 4),
                      a[mf][0], a[mf][1], a[mf][2], a[mf][3]);
            }
            uint32_t b[2][4];
#pragma unroll
            for (int nh = 0; nh < 2; ++nh) {
                int nr = warp_n * 32 + nh * 16 + (quad >> 1) * 8 + l8;
                int kc = ks * 2 + (quad & 1);
                ldmx4(bB + nr * 128 + ((kc ^ (nr & 7)) << 4),
                      b[nh][0], b[nh][1], b[nh][2], b[nh][3]);
            }
#pragma unroll
            for (int mf = 0; mf < MF; ++mf)
#pragma unroll
                for (int nf = 0; nf < 4; ++nf)
                    mma_fp16(acc[mf][nf], a[mf], b[nf >> 1][(nf & 1) * 2],
                             b[nf >> 1][(nf & 1) * 2 + 1]);
        }
        __syncthreads();
    }

    const int g = lane >> 2, tg = lane & 3;
#pragma unroll
    for (int mf = 0; mf < MF; ++mf)
#pragma unroll
        for (int nf = 0; nf < 4; ++nf) {
            int r0 = warp_m * (MT / 2) + mf * 16 + g;
            int col = warp_n * 32 + nf * 8 + tg * 2;
            *(float2*)&smf[r0 * 132 + col]       = make_float2(acc[mf][nf][0], acc[mf][nf][1]);
            *(float2*)&smf[(r0 + 8) * 132 + col] = make_float2(acc[mf][nf][2], acc[mf][nf][3]);
        }
    __syncthreads();

    float4 b4 = *(const float4*)&bias[n0 + lane * 4];
    const float* b4p = &b4.x;
    constexpr int RW = MT / 8;

    if (EPI == 0) {
#pragma unroll
        for (int it = 0; it < RW; ++it) {
            int r = wid * RW + it;
            int grow = m0 + r;
            float4 v = *(const float4*)&smf[r * 132 + lane * 4];
            float* vp = &v.x;
#pragma unroll
            for (int e = 0; e < 4; ++e) {
                float vv = vp[e] + b4p[e];
                if (ACT == 1) vv = gelu_exact(vv);
                vp[e] = vv;
            }
            if (WF32)
                *(float4*)(C + (size_t)grow * N + n0 + lane * 4) = v;
            if (WSP) {
                size_t base = (size_t)grow * 2 * N;
                int cc = n0 + lane * 4;
                __half* hp = Asp + base + cc;
                split4_store(vp, hp, hp + N);
            }
        }
    } else {
        float c_ = 0.f, sc_ = 0.f, maxn = 0.f;
        if (EPI == 2) { curvature(logc, c_, sc_); maxn = (1.0f - 1e-5f) / sc_; }
        float4 g4 = *(const float4*)&gg[lane * 4];
        float4 bt4 = *(const float4*)&bb[lane * 4];
        const float* g4p = &g4.x; const float* bt4p = &bt4.x;
#pragma unroll 1
        for (int it = 0; it < RW; ++it) {
            int r = wid * RW + it;
            int grow = m0 + r;
            float4 v = *(const float4*)&smf[r * 132 + lane * 4];
            float* vp = &v.x;
            float x[4];
            if (R != nullptr) {
                float4 rr = *(const float4*)&R[(size_t)grow * ND + lane * 4];
                const float* rrp = &rr.x;
#pragma unroll
                for (int e = 0; e < 4; ++e) x[e] = vp[e] + b4p[e] + rrp[e];
            } else {
#pragma unroll
                for (int e = 0; e < 4; ++e) x[e] = vp[e] + b4p[e];
            }
            float m = warp_sum(x[0] + x[1] + x[2] + x[3]) * (1.0f / 128.0f);
            float q = 0.f;
#pragma unroll
            for (int e = 0; e < 4; ++e) { x[e] -= m; q += x[e] * x[e]; }
            float var = warp_sum(q) * (1.0f / 128.0f);
            float rstd = rsqrtf(var + 1e-5f);
            float y[4];
#pragma unroll
            for (int e = 0; e < 4; ++e) y[e] = x[e] * rstd * g4p[e] + bt4p[e];

            if (EPI == 1) {
                *(float4*)(C + (size_t)grow * ND + lane * 4) = *(float4*)y;
                size_t base = (size_t)grow * 256;
                __half* hp = Asp + base + lane * 4;
                split4_store(y, hp, hp + 128);
            } else {
                float n2 = warp_sum(y[0]*y[0] + y[1]*y[1] + y[2]*y[2] + y[3]*y[3]);
                float vn = fmaxf(sqrtf(n2), 1e-10f);
                float kk = tanhf(sc_ * vn * 0.5f) / (sc_ * vn);
                float en = kk * vn;
                float scl = fminf(maxn / fmaxf(en, 1e-6f), 1.0f);
                float ke = kk * scl;
                float ee[4];
#pragma unroll
                for (int e = 0; e < 4; ++e) ee[e] = ke * y[e];
                *(float4*)(C + (size_t)grow * ND + lane * 4) = *(float4*)ee;
                pack4_store(y, Asp + (size_t)grow * 128 + lane * 4);
                if (lane == 0) {
                    float e2 = en * en * scl * scl;
                    e2o[grow] = e2;
                    deo[grow] = 1.0f - c_ * fminf(e2, 1.0f - 1e-5f);
                    keo[grow] = ke;
                }
            }
        }
    }
}

// ---------------- merged head: A persists, sequential z planes --------------
#define DB_OFF  32768
#define DS_OFF  65536
#define DSMEM   (65536 + 64 * 132 * 4)   // 99328

__global__ void __launch_bounds__(256, 2) dual_mma(
    const float* __restrict__ e2v, const float* __restrict__ dev,
    const float* __restrict__ kev, const float* __restrict__ logc,
    float* __restrict__ hyp, float* __restrict__ euc)
{
    extern __shared__ char smem[];
    float* smf = (float*)(smem + DS_OFF);
    const int tid = threadIdx.x, wid = tid >> 5, lane = tid & 31;
    const int m0 = blockIdx.y * 128, n0 = blockIdx.x * 128;
    const char* Ag  = (const char*)g_Ay;
    const char* B1g = (const char*)g_B1e;
    const char* B2g = (const char*)g_B2e;
    const uint32_t sbase = smem_u32(smem);
    const int warp_m = wid & 1, warp_n = wid >> 1;
    const int quad = lane >> 3, l8 = lane & 7;

    auto load_A = [&](int s) {
        const uint32_t sA = sbase + (uint32_t)s * 16384;
        const size_t kb = (size_t)s * 128;
#pragma unroll
        for (int j = 0; j < 4; ++j) {
            int idx = tid + 256 * j;
            int row = idx >> 3, ch = idx & 7;
            uint32_t so = row * 128 + ((ch ^ (row & 7)) << 4);
            cp_async16(sA + so, Ag + (size_t)(m0 + row) * 256 + kb + ch * 16);
        }
    };
    auto load_B = [&](const char* Bg, int s) {
        const uint32_t sB = sbase + DB_OFF + (uint32_t)s * 16384;
        const size_t kb = (size_t)s * 128;
#pragma unroll
        for (int j = 0; j < 4; ++j) {
            int idx = tid + 256 * j;
            int row = idx >> 3, ch = idx & 7;
            uint32_t so = row * 128 + ((ch ^ (row & 7)) << 4);
            cp_async16(sB + so, Bg + (size_t)(n0 + row) * 256 + kb + ch * 16);
        }
    };

    const int gc = n0 + lane * 4;
    const bool ok = gc < NC;
    float c_, sc_; curvature(logc, c_, sc_);
    const float inv2sc = 2.0f / sc_;
    const float slg = -inv2sc * 0.69314718055994531f;
    float p2c[4], dpc[4], ebc[4];
    {
        float4 p2 = *(const float4*)&g_p2[gc];
        float4 dp = *(const float4*)&g_dp[gc];
        float4 eb = *(const float4*)&g_eb[gc];
        p2c[0]=p2.x; p2c[1]=p2.y; p2c[2]=p2.z; p2c[3]=p2.w;
        dpc[0]=dp.x; dpc[1]=dp.y; dpc[2]=dp.z; dpc[3]=dp.w;
        ebc[0]=eb.x; ebc[1]=eb.y; ebc[2]=eb.z; ebc[3]=eb.w;
    }

    float acc[4][4][4];
    const int g = lane >> 2, tg = lane & 3;

    auto mainloop = [&]() {
#pragma unroll
        for (int mf = 0; mf < 4; ++mf)
#pragma unroll
            for (int nf = 0; nf < 4; ++nf)
#pragma unroll
                for (int e = 0; e < 4; ++e) acc[mf][nf][e] = 0.f;
#pragma unroll 1
        for (int s = 0; s < 2; ++s) {
            if (s == 0) asm volatile("cp.async.wait_group 1;" ::: "memory");
            else        asm volatile("cp.async.wait_group 0;" ::: "memory");
            __syncthreads();
            const uint32_t aB = sbase + (uint32_t)s * 16384;
            const uint32_t bB = sbase + DB_OFF + (uint32_t)s * 16384;
#pragma unroll
            for (int ks = 0; ks < 4; ++ks) {
                uint32_t a[4][4];
#pragma unroll
                for (int mf = 0; mf < 4; ++mf) {
                    int mr = warp_m * 64 + mf * 16 + (quad & 1) * 8 + l8;
                    int kc = ks * 2 + (quad >> 1);
                    ldmx4(aB + mr * 128 + ((kc ^ (mr & 7)) << 4),
                          a[mf][0], a[mf][1], a[mf][2], a[mf][3]);
                }
                uint32_t b[2][4];
#pragma unroll
                for (int nh = 0; nh < 2; ++nh) {
                    int nr = warp_n * 32 + nh * 16 + (quad >> 1) * 8 + l8;
                    int kc = ks * 2 + (quad & 1);
                    ldmx4(bB + nr * 128 + ((kc ^ (nr & 7)) << 4),
                          b[nh][0], b[nh][1], b[nh][2], b[nh][3]);
                }
#pragma unroll
                for (int mf = 0; mf < 4; ++mf)
#pragma unroll
                    for (int nf = 0; nf < 4; ++nf)
                        mma_fp16(acc[mf][nf], a[mf], b[nf >> 1][(nf & 1) * 2],
                                 b[nf >> 1][(nf & 1) * 2 + 1]);
            }
            __syncthreads();
        }
    };

    auto epilogue = [&](int z) {
        float* dst = z ? euc : hyp;
#pragma unroll 1
        for (int p = 0; p < 2; ++p) {
            if (warp_m == p) {
#pragma unroll
                for (int mf = 0; mf < 4; ++mf)
#pragma unroll
                    for (int nf = 0; nf < 4; ++nf) {
                        int r0 = mf * 16 + g;
                        int col = warp_n * 32 + nf * 8 + tg * 2;
                        *(float2*)&smf[r0 * 132 + col] =
                            make_float2(acc[mf][nf][0], acc[mf][nf][1]);
                        *(float2*)&smf[(r0 + 8) * 132 + col] =
                            make_float2(acc[mf][nf][2], acc[mf][nf][3]);
                    }
            }
            __syncthreads();
#pragma unroll 2
            for (int it = 0; it < 8; ++it) {
                int r = wid * 8 + it;
                int grow = m0 + p * 64 + r;
                float4 v = *(const float4*)&smf[r * 132 + lane * 4];
                float* vp = &v.x;
                if (z == 0) {
                    float e2r = e2v[grow], der = dev[grow];
                    float m2ke = -2.0f * kev[grow];
#pragma unroll
                    for (int e = 0; e < 4; ++e) {
                        float diff = fmaxf(fmaf(m2ke, vp[e], e2r + p2c[e]), 1e-10f);
                        float den  = fmaxf(der * dpc[e], 1e-6f);
                        float num  = fmaf(2.0f, diff, den);
                        float dist;
                        if (diff >= 32.0f * den) {
                            dist = slg * (__log2f(num) - __log2f(den) + 1.0f);
                        } else {
                            float arg = fmaxf(__fdividef(num, den), 1.0f + 1e-6f);
                            dist = -inv2sc * acoshf(arg);
                        }
                        vp[e] = dist;
                    }
                } else {
                    vp[0] += ebc[0]; vp[1] += ebc[1]; vp[2] += ebc[2]; vp[3] += ebc[3];
                }
                if (ok) __stcs((float4*)(dst + (size_t)grow * NC + gc), v);
            }
            __syncthreads();
        }
    };

    load_A(0); load_B(B1g, 0);
    asm volatile("cp.async.commit_group;" ::: "memory");
    load_A(1); load_B(B1g, 1);
    asm volatile("cp.async.commit_group;" ::: "memory");
    mainloop();
    load_B(B2g, 0);
    asm volatile("cp.async.commit_group;" ::: "memory");
    load_B(B2g, 1);
    asm volatile("cp.async.commit_group;" ::: "memory");
    epilogue(0);
    mainloop();
    epilogue(1);
}

// ------------------------------- launch -------------------------------------
extern "C" void kernel_launch(void* const* d_in, const int* in_sizes, int n_in,
                              void* d_out, int out_size)
{
    const float* x      = (const float*)d_in[0];
    const float* W1     = (const float*)d_in[1];
    const float* b1     = (const float*)d_in[2];
    const float* W2     = (const float*)d_in[3];
    const float* b2     = (const float*)d_in[4];
    const float* in_w   = (const float*)d_in[5];
    const float* in_b   = (const float*)d_in[6];
    const float* out_w  = (const float*)d_in[7];
    const float* out_b  = (const float*)d_in[8];
    const float* fw1    = (const float*)d_in[9];
    const float* fb1    = (const float*)d_in[10];
    const float* fw2    = (const float*)d_in[11];
    const float* fb2    = (const float*)d_in[12];
    const float* g1     = (const float*)d_in[13];
    const float* bt1    = (const float*)d_in[14];
    const float* g2     = (const float*)d_in[15];
    const float* bt2    = (const float*)d_in[16];
    const float* logc   = (const float*)d_in[17];
    const float* protos = (const float*)d_in[18];
    const float* euc_w  = (const float*)d_in[19];
    const float* euc_b  = (const float*)d_in[20];

    float *xs, *e2, *de, *ke, *W2c, *bc;
    __half *t1sp, *xssp, *hsp, *W1p, *W2cp, *fw1p, *fw2p, *Ay;
    cudaGetSymbolAddress((void**)&xs,   g_xs);
    cudaGetSymbolAddress((void**)&e2,   g_e2);
    cudaGetSymbolAddress((void**)&de,   g_de);
    cudaGetSymbolAddress((void**)&ke,   g_ke);
    cudaGetSymbolAddress((void**)&W2c,  g_W2c);
    cudaGetSymbolAddress((void**)&bc,   g_bc);
    cudaGetSymbolAddress((void**)&t1sp, g_t1sp);
    cudaGetSymbolAddress((void**)&xssp, g_xssp);
    cudaGetSymbolAddress((void**)&hsp,  g_hsp);
    cudaGetSymbolAddress((void**)&W1p,  g_W1p);
    cudaGetSymbolAddress((void**)&W2cp, g_W2cp);
    cudaGetSymbolAddress((void**)&fw1p, g_fw1p);
    cudaGetSymbolAddress((void**)&fw2p, g_fw2p);
    cudaGetSymbolAddress((void**)&Ay,   g_Ay);

    float* out = (float*)d_out;
    float* hyp = out;
    float* euc = out + (size_t)NB * NC;
    float* emb = out + (size_t)NB * NC * 2;

    static cudaStream_t s2 = nullptr;
    static cudaEvent_t evF = nullptr, evW1 = nullptr, evW = nullptr, evJ = nullptr;
    if (!s2) {
        cudaStreamCreateWithFlags(&s2, cudaStreamNonBlocking);
        cudaEventCreateWithFlags(&evF, cudaEventDisableTiming);
        cudaEventCreateWithFlags(&evW1, cudaEventDisableTiming);
        cudaEventCreateWithFlags(&evW, cudaEventDisableTiming);
        cudaEventCreateWithFlags(&evJ, cudaEventDisableTiming);
        cudaFuncSetAttribute(dual_mma, cudaFuncAttributeMaxDynamicSharedMemorySize, DSMEM);
        cudaFuncSetAttribute(hgemm<32,1,0,0,2,1>, cudaFuncAttributeMaxDynamicSharedMemorySize, HSMEM);
        cudaFuncSetAttribute(hgemm<32,0,1,0,0,0>, cudaFuncAttributeMaxDynamicSharedMemorySize, HSMEM);
        cudaFuncSetAttribute(hgemm<64,1,0,0,2,0>, cudaFuncAttributeMaxDynamicSharedMemorySize, HSMEM);
        cudaFuncSetAttribute(hgemm<32,0,2,0,0,0>, cudaFuncAttributeMaxDynamicSharedMemorySize, HSMEM);
    }

    // ---- fork: side stream does all weight/proto preps ----
    cudaEventRecord(evF, 0);
    cudaStreamWaitEvent(s2, evF, 0);
    wprep2<<<dim3(NIN / 32, 256 / 32), 256, 0, s2>>>(W1, W1p, NIN, 256);
    cudaEventRecord(evW1, s2);
    fold_w<<<ND + 1, 128, 0, s2>>>(in_w, out_w, in_b, out_b);
    fold2_w<<<257, 128, 0, s2>>>(W2, b2);
    wprep2<<<dim3(256 / 32, 128 / 32), 256, 0, s2>>>(W2c, W2cp, 256, 128);
    wprep2<<<dim3(128 / 32, 512 / 32), 256, 0, s2>>>(fw1, fw1p, 128, 512);
    wprep2<<<dim3(512 / 32, 128 / 32), 256, 0, s2>>>(fw2, fw2p, 512, 128);
    cudaEventRecord(evW, s2);
    proto_prep<<<NC2, 128, 0, s2>>>(protos, logc);
    euc_prep <<<NC2 / 64, 256, 0, s2>>>(euc_w, euc_b);
    cudaEventRecord(evJ, s2);

    // ---- main stream: front-end chain (x split fused into hgemm1) ----
    cudaStreamWaitEvent(0, evW1, 0);
    hgemm<32,1,0,0,2,1><<<dim3(2, NB / 32), 256, HSMEM>>>(
        nullptr, x, W1p, b1, nullptr, t1sp, nullptr, nullptr, nullptr,
        nullptr, nullptr, nullptr, nullptr, 2048, 256);
    cudaStreamWaitEvent(0, evW, 0);
    hgemm<32,0,1,0,0,0><<<dim3(1, NB / 32), 256, HSMEM>>>(
        t1sp, nullptr, W2cp, bc, xs, xssp, nullptr, g1, bt1,
        nullptr, nullptr, nullptr, nullptr, 512, 128);
    hgemm<64,1,0,0,2,0><<<dim3(4, NB / 64), 256, HSMEM>>>(
        xssp, nullptr, fw1p, fb1, nullptr, hsp, nullptr, nullptr, nullptr,
        nullptr, nullptr, nullptr, nullptr, 256, 512);
    hgemm<32,0,2,0,0,0><<<dim3(1, NB / 32), 256, HSMEM>>>(
        hsp, nullptr, fw2p, fb2, emb, Ay, xs, g2, bt2,
        logc, e2, de, ke, 1024, 128);

    // ---- join, then merged head ----
    cudaStreamWaitEvent(0, evJ, 0);
    dual_mma<<<dim3(NC2 / 128, NB / 128), 256, DSMEM>>>(e2, de, ke, logc, hyp, euc);
}